// round 1
// baseline (speedup 1.0000x reference)
#include <cuda_runtime.h>
#include <cstdint>
#include <cstdio>

#define B_  16
#define T_  512
#define V_  8192
#define E_  512
#define H_  1024
#define FH  4096   // 4*H
#define NBLK 128   // persistent recurrence blocks (must be < #SMs for co-residency)

// ---------------- device scratch (static; no allocations allowed) ----------------
__device__ float d_x[B_*T_*E_];            // 16.8 MB  embedded inputs [B*T, E]
__device__ float d_wxn[E_*FH];             // 8.4 MB
__device__ float d_whn[H_*FH];             // 16.8 MB
__device__ float d_wmxn[E_*H_];            // 2.1 MB
__device__ float d_wmhn[H_*H_];            // 4.2 MB
__device__ float d_zx[B_*T_*FH];           // 134 MB   x@wx_n + b
__device__ float d_mx[B_*T_*H_];           // 33.5 MB  x@wmx_n
__device__ float d_h[B_*H_];
__device__ float d_c[B_*H_];
__device__ float d_m[B_*H_];
__device__ float d_hs[B_*T_*H_];           // 33.5 MB  hidden states
__device__ float d_logits[(size_t)B_*T_*V_]; // 268 MB
__device__ float d_rownll[B_*T_];
__device__ unsigned g_barcnt;

// ---------------- weight norm: out[:,j] = w[:,j] / max(||w[:,j]||,1e-12) * g[j] ----
__global__ void colnorm_kernel(const float* __restrict__ w, const float* __restrict__ g,
                               float* __restrict__ out, int K, int N) {
    int j = blockIdx.x * blockDim.x + threadIdx.x;
    if (j >= N) return;
    float ss = 0.f;
    for (int k = 0; k < K; k++) { float v = w[k*N + j]; ss += v * v; }
    float nrm = sqrtf(ss);
    float scale = g[j] / fmaxf(nrm, 1e-12f);
    for (int k = 0; k < K; k++) out[k*N + j] = w[k*N + j] * scale;
}

// ---------------- embedding with padding_idx = 0 ----------------
__global__ void embed_kernel(const int* __restrict__ xs, const float* __restrict__ ew,
                             float* __restrict__ x) {
    int r = blockIdx.x;
    int idx = xs[r];
    const float4* src = (const float4*)(ew + (size_t)idx * E_);
    float4* dst = (float4*)(x + (size_t)r * E_);
    float4 v = src[threadIdx.x];                 // row 0 is valid memory
    if (idx == 0) v = make_float4(0.f, 0.f, 0.f, 0.f);
    dst[threadIdx.x] = v;
}

// ---------------- generic fp32 tiled GEMM: C = A[M,K] * B (+bias) -----------------
// TB=false: B is [K,N] row-major.  TB=true: B is [N,K] row-major (B^T multiply).
// All dims assumed multiples of 128 (true here: M=8192, N in {1024,4096,8192}, K in {512,1024}).
template<bool TB, bool BIAS>
__global__ void __launch_bounds__(256) gemm128(
    const float* __restrict__ A, const float* __restrict__ B,
    const float* __restrict__ bias, float* __restrict__ C,
    int M, int N, int K)
{
    __shared__ float As[8][128];
    __shared__ float Bs[8][128];
    const int bm = blockIdx.y * 128, bn = blockIdx.x * 128;
    const int tid = threadIdx.x;
    const int tx = tid & 15, ty = tid >> 4;     // 16x16 thread grid, 8x8 microtile
    float acc[8][8];
    #pragma unroll
    for (int i = 0; i < 8; i++)
        #pragma unroll
        for (int j = 0; j < 8; j++) acc[i][j] = 0.f;

    const int arow = tid >> 1, acol4 = (tid & 1) << 2;

    for (int k0 = 0; k0 < K; k0 += 8) {
        // A tile 128x8
        float4 av = *(const float4*)&A[(size_t)(bm + arow) * K + k0 + acol4];
        As[acol4+0][arow] = av.x; As[acol4+1][arow] = av.y;
        As[acol4+2][arow] = av.z; As[acol4+3][arow] = av.w;
        if (TB) {
            int n = tid >> 1, kk = (tid & 1) << 2;
            float4 bv = *(const float4*)&B[(size_t)(bn + n) * K + k0 + kk];
            Bs[kk+0][n] = bv.x; Bs[kk+1][n] = bv.y;
            Bs[kk+2][n] = bv.z; Bs[kk+3][n] = bv.w;
        } else {
            int kk = tid >> 5, c4 = (tid & 31) << 2;
            float4 bv = *(const float4*)&B[(size_t)(k0 + kk) * N + bn + c4];
            *(float4*)&Bs[kk][c4] = bv;
        }
        __syncthreads();
        #pragma unroll
        for (int kk = 0; kk < 8; kk++) {
            float ar[8], br[8];
            #pragma unroll
            for (int i = 0; i < 8; i++) ar[i] = As[kk][ty*8 + i];
            #pragma unroll
            for (int j = 0; j < 8; j++) br[j] = Bs[kk][tx*8 + j];
            #pragma unroll
            for (int i = 0; i < 8; i++)
                #pragma unroll
                for (int j = 0; j < 8; j++) acc[i][j] += ar[i] * br[j];
        }
        __syncthreads();
    }
    #pragma unroll
    for (int i = 0; i < 8; i++) {
        int row = bm + ty*8 + i;
        #pragma unroll
        for (int j = 0; j < 8; j += 4) {
            int col = bn + tx*8 + j;
            float4 v = make_float4(acc[i][j], acc[i][j+1], acc[i][j+2], acc[i][j+3]);
            if (BIAS) {
                v.x += bias[col];   v.y += bias[col+1];
                v.z += bias[col+2]; v.w += bias[col+3];
            }
            *(float4*)&C[(size_t)row * N + col] = v;
        }
    }
}

// ---------------- persistent recurrence kernel -------------------------------------
__global__ void reset_bar_kernel() { g_barcnt = 0u; }

__device__ __forceinline__ void gbar(unsigned target) {
    __threadfence();          // make this thread's global writes visible at L2
    __syncthreads();
    if (threadIdx.x == 0) {
        atomicAdd(&g_barcnt, 1u);
        volatile unsigned* p = &g_barcnt;
        while (*p < target) __nanosleep(64);
    }
    __syncthreads();
}

__global__ void __launch_bounds__(256) recur_kernel(
    const float* __restrict__ zx, const float* __restrict__ mxp,
    const float* __restrict__ wmhn, const float* __restrict__ whn,
    float* __restrict__ hs)
{
    const int bk = blockIdx.x, tid = threadIdx.x;
    __shared__ float red[256];
    __shared__ float zsm[512];   // [b(16)][q(4)][j0(8)]

    // zero this block's slice of h, c
    if (tid < 128) {
        int b = tid >> 3, j = (tid & 7) + bk * 8;
        d_h[b*H_ + j] = 0.f;
        d_c[b*H_ + j] = 0.f;
    }
    unsigned tgt = NBLK;
    gbar(tgt); tgt += NBLK;

    // phase A mapping: 256 threads = 128 outputs (b, j0) x 2 k-halves
    const int outA = tid >> 1, halfA = tid & 1;
    const int bA = outA >> 3, j0A = outA & 7, jA = bk*8 + j0A;
    // phase B mapping: (j0, q, b) with each thread handling batches b and b+8
    const int j0B = tid & 7, qB = (tid >> 3) & 3, bB = tid >> 5;   // bB in 0..7
    const int colB = bk*8 + j0B, zcolB = qB*H_ + colB;

    for (int t = 0; t < T_; t++) {
        // ---- phase A: m[b,j] = (h @ wmh_n)[b,j] * mx[b,t,j] ----
        {
            const float* hrow = d_h + bA*H_ + halfA*512;
            const float* wcol = wmhn + halfA*512*H_ + jA;
            float a0=0.f, a1=0.f, a2=0.f, a3=0.f;
            #pragma unroll 8
            for (int k = 0; k < 512; k += 4) {
                a0 += __ldcg(hrow + k+0) * __ldg(wcol + (k+0)*H_);
                a1 += __ldcg(hrow + k+1) * __ldg(wcol + (k+1)*H_);
                a2 += __ldcg(hrow + k+2) * __ldg(wcol + (k+2)*H_);
                a3 += __ldcg(hrow + k+3) * __ldg(wcol + (k+3)*H_);
            }
            red[tid] = (a0 + a1) + (a2 + a3);
            __syncthreads();
            if (halfA == 0) {
                float s = red[tid] + red[tid + 1];
                __stcg(&d_m[bA*H_ + jA], s * __ldg(&mxp[(size_t)(bA*T_ + t)*H_ + jA]));
            }
        }
        gbar(tgt); tgt += NBLK;

        // ---- phase B: z = zx_t + m @ wh_n ; gates; update c, h ----
        {
            const float* w  = whn + zcolB;
            const float* m0 = d_m + bB*H_;
            const float* m1 = d_m + (bB + 8)*H_;
            float p0=0.f, p1=0.f, r0=0.f, r1=0.f;
            #pragma unroll 8
            for (int k = 0; k < H_; k += 2) {
                float w0 = __ldg(w + (size_t)k*FH), w1 = __ldg(w + (size_t)(k+1)*FH);
                float a0 = __ldcg(m0 + k), a1 = __ldcg(m0 + k + 1);
                float b0 = __ldcg(m1 + k), b1 = __ldcg(m1 + k + 1);
                p0 += a0*w0; p1 += a1*w1;
                r0 += b0*w0; r1 += b1*w1;
            }
            float s0 = zx[(size_t)(bB*T_ + t)*FH + zcolB] + p0 + p1;
            float s1 = zx[(size_t)((bB+8)*T_ + t)*FH + zcolB] + r0 + r1;
            zsm[bB*32 + qB*8 + j0B]       = s0;
            zsm[(bB+8)*32 + qB*8 + j0B]   = s1;
            __syncthreads();
            if (tid < 128) {
                int b2 = tid >> 3, jj = tid & 7, col2 = bk*8 + jj;
                float zi = zsm[b2*32 +      jj];
                float zf = zsm[b2*32 +  8 + jj];
                float zo = zsm[b2*32 + 16 + jj];
                float zu = zsm[b2*32 + 24 + jj];
                float ig = 1.f / (1.f + expf(-zi));
                float fg = 1.f / (1.f + expf(-zf));
                float og = 1.f / (1.f + expf(-zo));
                float ug = tanhf(zu);
                float c  = fg * d_c[b2*H_ + col2] + ig * ug;
                float h  = og * tanhf(c);
                d_c[b2*H_ + col2] = c;
                __stcg(&d_h[b2*H_ + col2], h);
                hs[(size_t)(b2*T_ + t)*H_ + col2] = h;
            }
        }
        gbar(tgt); tgt += NBLK;
    }
}

// ---------------- per-row log-softmax NLL ------------------------------------------
__global__ void nll_kernel(const float* __restrict__ logits, const int* __restrict__ ys,
                           float* __restrict__ rownll) {
    __shared__ float sred[256];
    int row = blockIdx.x, tid = threadIdx.x;
    const float* l = logits + (size_t)row * V_;
    float m = -3.4e38f;
    for (int v = tid; v < V_; v += 256) m = fmaxf(m, l[v]);
    sred[tid] = m; __syncthreads();
    for (int s = 128; s > 0; s >>= 1) {
        if (tid < s) sred[tid] = fmaxf(sred[tid], sred[tid + s]);
        __syncthreads();
    }
    float rowmax = sred[0]; __syncthreads();
    float sum = 0.f;
    for (int v = tid; v < V_; v += 256) sum += expf(l[v] - rowmax);
    sred[tid] = sum; __syncthreads();
    for (int s = 128; s > 0; s >>= 1) {
        if (tid < s) sred[tid] += sred[tid + s];
        __syncthreads();
    }
    if (tid == 0)
        rownll[row] = -(l[ys[row]] - rowmax - logf(sred[0]));
}

__global__ void mean_kernel(const float* __restrict__ rownll, float* __restrict__ out) {
    __shared__ float sred[256];
    int tid = threadIdx.x;
    float s = 0.f;
    for (int i = tid; i < B_*T_; i += 256) s += rownll[i];
    sred[tid] = s; __syncthreads();
    for (int k = 128; k > 0; k >>= 1) {
        if (tid < k) sred[tid] += sred[tid + k];
        __syncthreads();
    }
    if (tid == 0) out[0] = sred[0] / (float)(B_*T_);
}

// ---------------- launcher ----------------------------------------------------------
extern "C" void kernel_launch(void* const* d_in, const int* in_sizes, int n_in,
                              void* d_out, int out_size) {
    (void)in_sizes; (void)n_in; (void)out_size;
    const int*   xs      = (const int*)  d_in[0];
    const int*   ys      = (const int*)  d_in[1];
    const float* embed_w = (const float*)d_in[2];
    const float* wx      = (const float*)d_in[3];
    const float* wh      = (const float*)d_in[4];
    const float* wmx     = (const float*)d_in[5];
    const float* wmh     = (const float*)d_in[6];
    const float* bb      = (const float*)d_in[7];
    const float* gx      = (const float*)d_in[8];
    const float* gh      = (const float*)d_in[9];
    const float* gmx     = (const float*)d_in[10];
    const float* gmh     = (const float*)d_in[11];
    const float* pred_w  = (const float*)d_in[12];
    const float* pred_b  = (const float*)d_in[13];
    float* out = (float*)d_out;

    float *p_x, *p_wxn, *p_whn, *p_wmxn, *p_wmhn, *p_zx, *p_mx, *p_hs, *p_logits, *p_rownll;
    cudaGetSymbolAddress((void**)&p_x,      d_x);
    cudaGetSymbolAddress((void**)&p_wxn,    d_wxn);
    cudaGetSymbolAddress((void**)&p_whn,    d_whn);
    cudaGetSymbolAddress((void**)&p_wmxn,   d_wmxn);
    cudaGetSymbolAddress((void**)&p_wmhn,   d_wmhn);
    cudaGetSymbolAddress((void**)&p_zx,     d_zx);
    cudaGetSymbolAddress((void**)&p_mx,     d_mx);
    cudaGetSymbolAddress((void**)&p_hs,     d_hs);
    cudaGetSymbolAddress((void**)&p_logits, d_logits);
    cudaGetSymbolAddress((void**)&p_rownll, d_rownll);

    // weight norm
    colnorm_kernel<<<FH/256, 256>>>(wx,  gx,  p_wxn,  E_, FH);
    colnorm_kernel<<<FH/256, 256>>>(wh,  gh,  p_whn,  H_, FH);
    colnorm_kernel<<<H_/256, 256>>>(wmx, gmx, p_wmxn, E_, H_);
    colnorm_kernel<<<H_/256, 256>>>(wmh, gmh, p_wmhn, H_, H_);
    // embedding
    embed_kernel<<<B_*T_, 128>>>(xs, embed_w, p_x);
    // input-dependent projections
    gemm128<false, true ><<<dim3(FH/128, (B_*T_)/128), 256>>>(p_x, p_wxn,  bb, p_zx, B_*T_, FH, E_);
    gemm128<false, false><<<dim3(H_/128, (B_*T_)/128), 256>>>(p_x, p_wmxn, (const float*)nullptr, p_mx, B_*T_, H_, E_);
    // sequential recurrence (persistent kernel with grid barrier)
    reset_bar_kernel<<<1, 1>>>();
    recur_kernel<<<NBLK, 256>>>(p_zx, p_mx, p_wmhn, p_whn, p_hs);
    // output logits + loss
    gemm128<true, true><<<dim3(V_/128, (B_*T_)/128), 256>>>(p_hs, pred_w, pred_b, p_logits, B_*T_, V_, H_);
    nll_kernel<<<B_*T_, 256>>>(p_logits, ys, p_rownll);
    mean_kernel<<<1, 256>>>(p_rownll, out);
}

// round 2
// speedup vs baseline: 2.3307x; 2.3307x over previous
#include <cuda_runtime.h>
#include <cstdint>

#define B_  16
#define T_  512
#define V_  8192
#define E_  512
#define H_  1024
#define FH  4096
#define NBLK 128

// ---------------- device scratch ----------------
__device__ float d_x[B_*T_*E_];
__device__ float d_wxn[E_*FH];
__device__ float d_whnT[(size_t)FH*H_];      // transposed + normalized: [4096][1024]
__device__ float d_wmxn[E_*H_];
__device__ float d_wmhnT[H_*H_];             // transposed + normalized: [1024][1024]
__device__ float d_nwx[FH], d_nwh[FH], d_nwmx[H_], d_nwmh[H_];
__device__ float d_zx[(size_t)B_*T_*FH];
__device__ float d_mx[B_*T_*H_];
__device__ float d_h[B_*H_];
__device__ float d_mt[H_*B_];                // m transposed [j][b]
__device__ float d_hs[B_*T_*H_];
__device__ float d_logits[(size_t)B_*T_*V_];
__device__ float d_rownll[B_*T_];
__device__ unsigned g_barcnt;

// ---------------- weight norm: split-K sumsq + scale ----------------
__global__ void zero_norms_kernel() {
    int i = blockIdx.x * 256 + threadIdx.x;
    if (i < FH) { d_nwx[i] = 0.f; d_nwh[i] = 0.f; }
    if (i < H_) { d_nwmx[i] = 0.f; d_nwmh[i] = 0.f; }
}

__global__ void sumsq_kernel(const float* __restrict__ w, float* __restrict__ nrm,
                             int K, int N) {
    int j = blockIdx.x * 256 + threadIdx.x;
    int k0 = blockIdx.y * 128;
    float ss = 0.f;
    #pragma unroll 4
    for (int k = k0; k < k0 + 128; k++) { float v = w[(size_t)k*N + j]; ss += v*v; }
    atomicAdd(&nrm[j], ss);
}

__global__ void scale_plain_kernel(const float* __restrict__ w, const float* __restrict__ g,
                                   const float* __restrict__ nrm, float* __restrict__ out,
                                   int N, int total) {
    int i = blockIdx.x * 256 + threadIdx.x;
    if (i >= total) return;
    int j = i % N;
    float s = g[j] / fmaxf(sqrtf(nrm[j]), 1e-12f);
    out[i] = w[i] * s;
}

// out[n][k] = w[k][n] * g[n]/max(||w[:,n]||,eps)
__global__ void scaleT_kernel(const float* __restrict__ w, const float* __restrict__ g,
                              const float* __restrict__ nrm, float* __restrict__ out,
                              int K, int N) {
    __shared__ float tile[32][33];
    int n0 = blockIdx.x * 32, k0 = blockIdx.y * 32;
    int tx = threadIdx.x, ty = threadIdx.y;           // 32 x 8
    for (int r = ty; r < 32; r += 8)
        tile[r][tx] = w[(size_t)(k0 + r)*N + n0 + tx];
    __syncthreads();
    for (int r = ty; r < 32; r += 8) {
        int n = n0 + r;
        float s = g[n] / fmaxf(sqrtf(nrm[n]), 1e-12f);
        out[(size_t)n*K + k0 + tx] = tile[tx][r] * s;
    }
}

// ---------------- embedding, padding_idx = 0 ----------------
__global__ void embed_kernel(const int* __restrict__ xs, const float* __restrict__ ew,
                             float* __restrict__ x) {
    int r = blockIdx.x;
    int idx = xs[r];
    const float4* src = (const float4*)(ew + (size_t)idx * E_);
    float4* dst = (float4*)(x + (size_t)r * E_);
    float4 v = src[threadIdx.x];
    if (idx == 0) v = make_float4(0.f, 0.f, 0.f, 0.f);
    dst[threadIdx.x] = v;
}

// ---------------- fp32 tiled GEMM (unchanged from R0) ----------------
template<bool TB, bool BIAS>
__global__ void __launch_bounds__(256) gemm128(
    const float* __restrict__ A, const float* __restrict__ B,
    const float* __restrict__ bias, float* __restrict__ C,
    int M, int N, int K)
{
    __shared__ float As[8][128];
    __shared__ float Bs[8][128];
    const int bm = blockIdx.y * 128, bn = blockIdx.x * 128;
    const int tid = threadIdx.x;
    const int tx = tid & 15, ty = tid >> 4;
    float acc[8][8];
    #pragma unroll
    for (int i = 0; i < 8; i++)
        #pragma unroll
        for (int j = 0; j < 8; j++) acc[i][j] = 0.f;

    const int arow = tid >> 1, acol4 = (tid & 1) << 2;

    for (int k0 = 0; k0 < K; k0 += 8) {
        float4 av = *(const float4*)&A[(size_t)(bm + arow) * K + k0 + acol4];
        As[acol4+0][arow] = av.x; As[acol4+1][arow] = av.y;
        As[acol4+2][arow] = av.z; As[acol4+3][arow] = av.w;
        if (TB) {
            int n = tid >> 1, kk = (tid & 1) << 2;
            float4 bv = *(const float4*)&B[(size_t)(bn + n) * K + k0 + kk];
            Bs[kk+0][n] = bv.x; Bs[kk+1][n] = bv.y;
            Bs[kk+2][n] = bv.z; Bs[kk+3][n] = bv.w;
        } else {
            int kk = tid >> 5, c4 = (tid & 31) << 2;
            float4 bv = *(const float4*)&B[(size_t)(k0 + kk) * N + bn + c4];
            *(float4*)&Bs[kk][c4] = bv;
        }
        __syncthreads();
        #pragma unroll
        for (int kk = 0; kk < 8; kk++) {
            float ar[8], br[8];
            #pragma unroll
            for (int i = 0; i < 8; i++) ar[i] = As[kk][ty*8 + i];
            #pragma unroll
            for (int j = 0; j < 8; j++) br[j] = Bs[kk][tx*8 + j];
            #pragma unroll
            for (int i = 0; i < 8; i++)
                #pragma unroll
                for (int j = 0; j < 8; j++) acc[i][j] += ar[i] * br[j];
        }
        __syncthreads();
    }
    #pragma unroll
    for (int i = 0; i < 8; i++) {
        int row = bm + ty*8 + i;
        #pragma unroll
        for (int j = 0; j < 8; j += 4) {
            int col = bn + tx*8 + j;
            float4 v = make_float4(acc[i][j], acc[i][j+1], acc[i][j+2], acc[i][j+3]);
            if (BIAS) {
                v.x += bias[col];   v.y += bias[col+1];
                v.z += bias[col+2]; v.w += bias[col+3];
            }
            *(float4*)&C[(size_t)row * N + col] = v;
        }
    }
}

// ---------------- persistent recurrence ----------------
__global__ void reset_bar_kernel() { g_barcnt = 0u; }

__device__ __forceinline__ void gbar(unsigned target) {
    __threadfence();
    __syncthreads();
    if (threadIdx.x == 0) {
        atomicAdd(&g_barcnt, 1u);
        volatile unsigned* p = &g_barcnt;
        while (*p < target) __nanosleep(32);
    }
    __syncthreads();
}

// dyn smem layout (floats):
//   [0, 16384)      s_stage : phase A = h[b][k] flat ; phase B = m_t[k][b] flat
//   aliased after compute-B sync:
//     [0, 4608)     part[(ci*16+b)*9 + ks]
//     [8192, 8704)  zz[b*32 + ci]
//   [16384, 16640)  redA[256]
#define SM_STAGE 0
#define SM_PART  0
#define SM_ZZ    8192
#define SM_RED   16384
#define SM_FLOATS (16384 + 256)

__global__ void __launch_bounds__(256) recur_kernel(
    const float* __restrict__ zx, const float* __restrict__ mxp,
    const float* __restrict__ wmhnT, const float* __restrict__ whnT,
    float* __restrict__ hs)
{
    extern __shared__ float sm[];
    const int bk = blockIdx.x, tid = threadIdx.x;

    // zero h slice
    if (tid < 128) d_h[bk*128 + tid] = 0.f;
    unsigned tgt = NBLK;
    gbar(tgt); tgt += NBLK;

    // phase A mapping
    const int outA = tid >> 1, halfA = tid & 1;
    const int bA = outA >> 3, j0A = outA & 7;
    const int jA = bk*8 + j0A;
    // phase B mapping
    const int ksB = tid >> 5, ciB = tid & 31;
    const int qB = ciB >> 3, j0B = ciB & 7;
    const int colB = qB*H_ + bk*8 + j0B;
    // gate-thread state (tid < 128): b = tid>>3, j0 = tid&7
    const int bG = tid >> 3, j0G = tid & 7;
    float creg = 0.f;

    for (int t = 0; t < T_; t++) {
        // ---- stage h into smem (L2-coherent loads) ----
        {
            float4* dst = (float4*)(sm + SM_STAGE);
            const float4* src = (const float4*)d_h;
            #pragma unroll
            for (int i = tid; i < 4096; i += 256) dst[i] = __ldcg(src + i);
        }
        __syncthreads();

        // ---- phase A: m[b,j] = (h @ wmh_n)[b,j] * mx[b,t,j] ----
        {
            const float4* hp = (const float4*)(sm + SM_STAGE + bA*H_ + halfA*512);
            const float4* wp = (const float4*)(wmhnT + (size_t)jA*H_ + halfA*512);
            float ax=0.f, ay=0.f, az=0.f, aw=0.f;
            #pragma unroll 8
            for (int i = 0; i < 128; i++) {
                float4 hv = hp[i];
                float4 wv = __ldg(wp + i);
                ax += hv.x*wv.x; ay += hv.y*wv.y;
                az += hv.z*wv.z; aw += hv.w*wv.w;
            }
            sm[SM_RED + tid] = (ax + ay) + (az + aw);
        }
        __syncthreads();
        if (halfA == 0) {
            float s = sm[SM_RED + tid] + sm[SM_RED + tid + 1];
            float mxv = __ldg(&mxp[(size_t)(bA*T_ + t)*H_ + jA]);
            __stcg(&d_mt[jA*B_ + bA], s * mxv);
        }
        gbar(tgt); tgt += NBLK;

        // ---- stage m_t into smem ----
        {
            float4* dst = (float4*)(sm + SM_STAGE);
            const float4* src = (const float4*)d_mt;
            #pragma unroll
            for (int i = tid; i < 4096; i += 256) dst[i] = __ldcg(src + i);
        }
        __syncthreads();

        // ---- phase B: z = zx_t + m @ wh_n ----
        float acc[16];
        #pragma unroll
        for (int b = 0; b < 16; b++) acc[b] = 0.f;
        {
            const float4* wp = (const float4*)(whnT + (size_t)colB*H_ + ksB*128);
            const float* mp = sm + SM_STAGE + ksB*128*B_;
            #pragma unroll 4
            for (int k4 = 0; k4 < 32; k4++) {
                float4 wv = __ldg(wp + k4);
                #pragma unroll
                for (int u = 0; u < 4; u++) {
                    float wk = (u==0) ? wv.x : (u==1) ? wv.y : (u==2) ? wv.z : wv.w;
                    const float4* m4 = (const float4*)(mp + (k4*4 + u)*B_);
                    float4 m0 = m4[0], m1 = m4[1], m2 = m4[2], m3 = m4[3];
                    acc[0]  += m0.x*wk; acc[1]  += m0.y*wk; acc[2]  += m0.z*wk; acc[3]  += m0.w*wk;
                    acc[4]  += m1.x*wk; acc[5]  += m1.y*wk; acc[6]  += m1.z*wk; acc[7]  += m1.w*wk;
                    acc[8]  += m2.x*wk; acc[9]  += m2.y*wk; acc[10] += m2.z*wk; acc[11] += m2.w*wk;
                    acc[12] += m3.x*wk; acc[13] += m3.y*wk; acc[14] += m3.z*wk; acc[15] += m3.w*wk;
                }
            }
        }
        __syncthreads();   // all reads of s_stage done before aliasing as part[]
        #pragma unroll
        for (int b = 0; b < 16; b++)
            sm[SM_PART + (ciB*16 + b)*9 + ksB] = acc[b];
        __syncthreads();

        // ---- reduce over kslices + add zx ----
        #pragma unroll
        for (int o = 0; o < 2; o++) {
            int out = tid + o*256;
            int ci = out >> 4, b = out & 15;
            const float* p = sm + SM_PART + (ci*16 + b)*9;
            float s = ((p[0]+p[1]) + (p[2]+p[3])) + ((p[4]+p[5]) + (p[6]+p[7]));
            int q = ci >> 3, j0 = ci & 7;
            float zv = __ldg(&zx[(size_t)(b*T_ + t)*FH + q*H_ + bk*8 + j0]);
            sm[SM_ZZ + b*32 + ci] = zv + s;
        }
        __syncthreads();

        // ---- gates + state update (tid < 128) ----
        if (tid < 128) {
            float zi = sm[SM_ZZ + bG*32 +      j0G];
            float zf = sm[SM_ZZ + bG*32 +  8 + j0G];
            float zo = sm[SM_ZZ + bG*32 + 16 + j0G];
            float zu = sm[SM_ZZ + bG*32 + 24 + j0G];
            float ig = 1.f / (1.f + expf(-zi));
            float fg = 1.f / (1.f + expf(-zf));
            float og = 1.f / (1.f + expf(-zo));
            float ug = tanhf(zu);
            creg = fg * creg + ig * ug;
            float h = og * tanhf(creg);
            int col = bk*8 + j0G;
            __stcg(&d_h[bG*H_ + col], h);
            hs[(size_t)(bG*T_ + t)*H_ + col] = h;
        }
        gbar(tgt); tgt += NBLK;
    }
}

// ---------------- log-softmax NLL ----------------
__global__ void nll_kernel(const float* __restrict__ logits, const int* __restrict__ ys,
                           float* __restrict__ rownll) {
    __shared__ float sred[256];
    int row = blockIdx.x, tid = threadIdx.x;
    const float* l = logits + (size_t)row * V_;
    float m = -3.4e38f;
    for (int v = tid; v < V_; v += 256) m = fmaxf(m, l[v]);
    sred[tid] = m; __syncthreads();
    for (int s = 128; s > 0; s >>= 1) {
        if (tid < s) sred[tid] = fmaxf(sred[tid], sred[tid + s]);
        __syncthreads();
    }
    float rowmax = sred[0]; __syncthreads();
    float sum = 0.f;
    for (int v = tid; v < V_; v += 256) sum += expf(l[v] - rowmax);
    sred[tid] = sum; __syncthreads();
    for (int s = 128; s > 0; s >>= 1) {
        if (tid < s) sred[tid] += sred[tid + s];
        __syncthreads();
    }
    if (tid == 0)
        rownll[row] = -(l[ys[row]] - rowmax - logf(sred[0]));
}

__global__ void mean_kernel(const float* __restrict__ rownll, float* __restrict__ out) {
    __shared__ float sred[256];
    int tid = threadIdx.x;
    float s = 0.f;
    for (int i = tid; i < B_*T_; i += 256) s += rownll[i];
    sred[tid] = s; __syncthreads();
    for (int k = 128; k > 0; k >>= 1) {
        if (tid < k) sred[tid] += sred[tid + k];
        __syncthreads();
    }
    if (tid == 0) out[0] = sred[0] / (float)(B_*T_);
}

// ---------------- launcher ----------------
extern "C" void kernel_launch(void* const* d_in, const int* in_sizes, int n_in,
                              void* d_out, int out_size) {
    (void)in_sizes; (void)n_in; (void)out_size;
    const int*   xs      = (const int*)  d_in[0];
    const int*   ys      = (const int*)  d_in[1];
    const float* embed_w = (const float*)d_in[2];
    const float* wx      = (const float*)d_in[3];
    const float* wh      = (const float*)d_in[4];
    const float* wmx     = (const float*)d_in[5];
    const float* wmh     = (const float*)d_in[6];
    const float* bb      = (const float*)d_in[7];
    const float* gx      = (const float*)d_in[8];
    const float* gh      = (const float*)d_in[9];
    const float* gmx     = (const float*)d_in[10];
    const float* gmh     = (const float*)d_in[11];
    const float* pred_w  = (const float*)d_in[12];
    const float* pred_b  = (const float*)d_in[13];
    float* out = (float*)d_out;

    float *p_x, *p_wxn, *p_whnT, *p_wmxn, *p_wmhnT, *p_zx, *p_mx, *p_hs, *p_logits, *p_rownll;
    float *p_nwx, *p_nwh, *p_nwmx, *p_nwmh;
    cudaGetSymbolAddress((void**)&p_x,      d_x);
    cudaGetSymbolAddress((void**)&p_wxn,    d_wxn);
    cudaGetSymbolAddress((void**)&p_whnT,   d_whnT);
    cudaGetSymbolAddress((void**)&p_wmxn,   d_wmxn);
    cudaGetSymbolAddress((void**)&p_wmhnT,  d_wmhnT);
    cudaGetSymbolAddress((void**)&p_zx,     d_zx);
    cudaGetSymbolAddress((void**)&p_mx,     d_mx);
    cudaGetSymbolAddress((void**)&p_hs,     d_hs);
    cudaGetSymbolAddress((void**)&p_logits, d_logits);
    cudaGetSymbolAddress((void**)&p_rownll, d_rownll);
    cudaGetSymbolAddress((void**)&p_nwx,    d_nwx);
    cudaGetSymbolAddress((void**)&p_nwh,    d_nwh);
    cudaGetSymbolAddress((void**)&p_nwmx,   d_nwmx);
    cudaGetSymbolAddress((void**)&p_nwmh,   d_nwmh);

    static bool attr_set = false;
    if (!attr_set) {
        cudaFuncSetAttribute(recur_kernel, cudaFuncAttributeMaxDynamicSharedMemorySize,
                             SM_FLOATS * sizeof(float));
        attr_set = true;
    }

    // weight norm (split-K sumsq, then scale / scale+transpose)
    zero_norms_kernel<<<16, 256>>>();
    sumsq_kernel<<<dim3(FH/256, E_/128), 256>>>(wx,  p_nwx,  E_, FH);
    sumsq_kernel<<<dim3(FH/256, H_/128), 256>>>(wh,  p_nwh,  H_, FH);
    sumsq_kernel<<<dim3(H_/256, E_/128), 256>>>(wmx, p_nwmx, E_, H_);
    sumsq_kernel<<<dim3(H_/256, H_/128), 256>>>(wmh, p_nwmh, H_, H_);
    scale_plain_kernel<<<(E_*FH)/256, 256>>>(wx,  gx,  p_nwx,  p_wxn,  FH, E_*FH);
    scale_plain_kernel<<<(E_*H_)/256, 256>>>(wmx, gmx, p_nwmx, p_wmxn, H_, E_*H_);
    scaleT_kernel<<<dim3(FH/32, H_/32), dim3(32,8)>>>(wh,  gh,  p_nwh,  p_whnT,  H_, FH);
    scaleT_kernel<<<dim3(H_/32, H_/32), dim3(32,8)>>>(wmh, gmh, p_nwmh, p_wmhnT, H_, H_);

    // embedding
    embed_kernel<<<B_*T_, 128>>>(xs, embed_w, p_x);

    // input-dependent projections
    gemm128<false, true ><<<dim3(FH/128, (B_*T_)/128), 256>>>(p_x, p_wxn,  bb, p_zx, B_*T_, FH, E_);
    gemm128<false, false><<<dim3(H_/128, (B_*T_)/128), 256>>>(p_x, p_wmxn, (const float*)nullptr, p_mx, B_*T_, H_, E_);

    // recurrence
    reset_bar_kernel<<<1, 1>>>();
    recur_kernel<<<NBLK, 256, SM_FLOATS * sizeof(float)>>>(p_zx, p_mx, p_wmhnT, p_whnT, p_hs);

    // logits + loss
    gemm128<true, true><<<dim3(V_/128, (B_*T_)/128), 256>>>(p_hs, pred_w, pred_b, p_logits, B_*T_, V_, H_);
    nll_kernel<<<B_*T_, 256>>>(p_logits, ys, p_rownll);
    mean_kernel<<<1, 256>>>(p_rownll, out);
}

// round 3
// speedup vs baseline: 3.9126x; 1.6787x over previous
#include <cuda_runtime.h>
#include <cstdint>

#define B_  16
#define T_  512
#define V_  8192
#define E_  512
#define H_  1024
#define FH  4096
#define NBLK 128

// ---------------- device scratch ----------------
__device__ float d_x[B_*T_*E_];
__device__ float d_wxn[E_*FH];
__device__ float d_whnT[(size_t)FH*H_];      // transposed + normalized: [4096][1024]
__device__ float d_wmxn[E_*H_];
__device__ float d_wmhnT[H_*H_];             // transposed + normalized: [1024][1024]
__device__ float d_nwx[FH], d_nwh[FH], d_nwmx[H_], d_nwmh[H_];
__device__ float d_zx[(size_t)B_*T_*FH];
__device__ float d_mx[B_*T_*H_];
__device__ float d_h[B_*H_];
__device__ float d_mt[H_*B_];                // m transposed [j][b]
__device__ float d_hs[B_*T_*H_];
__device__ float d_logits[(size_t)B_*T_*V_];
__device__ float d_rownll[B_*T_];
__device__ unsigned g_barcnt;

// ---------------- weight norm ----------------
__global__ void zero_norms_kernel() {
    int i = blockIdx.x * 256 + threadIdx.x;
    if (i < FH) { d_nwx[i] = 0.f; d_nwh[i] = 0.f; }
    if (i < H_) { d_nwmx[i] = 0.f; d_nwmh[i] = 0.f; }
}

__global__ void sumsq_kernel(const float* __restrict__ w, float* __restrict__ nrm,
                             int K, int N) {
    int j = blockIdx.x * 256 + threadIdx.x;
    int k0 = blockIdx.y * 128;
    float ss = 0.f;
    #pragma unroll 4
    for (int k = k0; k < k0 + 128; k++) { float v = w[(size_t)k*N + j]; ss += v*v; }
    atomicAdd(&nrm[j], ss);
}

__global__ void scale_plain_kernel(const float* __restrict__ w, const float* __restrict__ g,
                                   const float* __restrict__ nrm, float* __restrict__ out,
                                   int N, int total) {
    int i = blockIdx.x * 256 + threadIdx.x;
    if (i >= total) return;
    int j = i % N;
    float s = g[j] / fmaxf(sqrtf(nrm[j]), 1e-12f);
    out[i] = w[i] * s;
}

__global__ void scaleT_kernel(const float* __restrict__ w, const float* __restrict__ g,
                              const float* __restrict__ nrm, float* __restrict__ out,
                              int K, int N) {
    __shared__ float tile[32][33];
    int n0 = blockIdx.x * 32, k0 = blockIdx.y * 32;
    int tx = threadIdx.x, ty = threadIdx.y;           // 32 x 8
    for (int r = ty; r < 32; r += 8)
        tile[r][tx] = w[(size_t)(k0 + r)*N + n0 + tx];
    __syncthreads();
    for (int r = ty; r < 32; r += 8) {
        int n = n0 + r;
        float s = g[n] / fmaxf(sqrtf(nrm[n]), 1e-12f);
        out[(size_t)n*K + k0 + tx] = tile[tx][r] * s;
    }
}

// ---------------- embedding, padding_idx = 0 ----------------
__global__ void embed_kernel(const int* __restrict__ xs, const float* __restrict__ ew,
                             float* __restrict__ x) {
    int r = blockIdx.x;
    int idx = xs[r];
    const float4* src = (const float4*)(ew + (size_t)idx * E_);
    float4* dst = (float4*)(x + (size_t)r * E_);
    float4 v = src[threadIdx.x];
    if (idx == 0) v = make_float4(0.f, 0.f, 0.f, 0.f);
    dst[threadIdx.x] = v;
}

// ---------------- fp32 tiled GEMM v2 (conflict-free frags + reg prefetch) --------
template<bool TB, bool BIAS>
__global__ void __launch_bounds__(256, 2) gemm128(
    const float* __restrict__ A, const float* __restrict__ B,
    const float* __restrict__ bias, float* __restrict__ C,
    int M, int N, int K)
{
    __shared__ float As[8][128];
    __shared__ float Bs[8][128];
    const int bm = blockIdx.y * 128, bn = blockIdx.x * 128;
    const int tid = threadIdx.x;
    const int tx = tid & 15, ty = tid >> 4;
    float acc[8][8];
    #pragma unroll
    for (int i = 0; i < 8; i++)
        #pragma unroll
        for (int j = 0; j < 8; j++) acc[i][j] = 0.f;

    const int arow = tid >> 1, acol4 = (tid & 1) << 2;
    const int bn_row = tid >> 1, bk4 = (tid & 1) << 2;        // TB=true loader
    const int bkk = tid >> 5, bc4 = (tid & 31) << 2;          // TB=false loader

    float4 av, bv;
    // prologue loads (k0 = 0)
    av = *(const float4*)&A[(size_t)(bm + arow) * K + acol4];
    if (TB) bv = *(const float4*)&B[(size_t)(bn + bn_row) * K + bk4];
    else    bv = *(const float4*)&B[(size_t)bkk * N + bn + bc4];

    for (int k0 = 0; k0 < K; k0 += 8) {
        As[acol4+0][arow] = av.x; As[acol4+1][arow] = av.y;
        As[acol4+2][arow] = av.z; As[acol4+3][arow] = av.w;
        if (TB) {
            Bs[bk4+0][bn_row] = bv.x; Bs[bk4+1][bn_row] = bv.y;
            Bs[bk4+2][bn_row] = bv.z; Bs[bk4+3][bn_row] = bv.w;
        } else {
            *(float4*)&Bs[bkk][bc4] = bv;
        }
        __syncthreads();
        if (k0 + 8 < K) {
            av = *(const float4*)&A[(size_t)(bm + arow) * K + (k0+8) + acol4];
            if (TB) bv = *(const float4*)&B[(size_t)(bn + bn_row) * K + (k0+8) + bk4];
            else    bv = *(const float4*)&B[(size_t)((k0+8) + bkk) * N + bn + bc4];
        }
        #pragma unroll
        for (int kk = 0; kk < 8; kk++) {
            float4 a0 = *(const float4*)&As[kk][ty*4];
            float4 a1 = *(const float4*)&As[kk][64 + ty*4];
            float4 b0 = *(const float4*)&Bs[kk][tx*4];
            float4 b1 = *(const float4*)&Bs[kk][64 + tx*4];
            float ar[8] = {a0.x,a0.y,a0.z,a0.w, a1.x,a1.y,a1.z,a1.w};
            float br[8] = {b0.x,b0.y,b0.z,b0.w, b1.x,b1.y,b1.z,b1.w};
            #pragma unroll
            for (int i = 0; i < 8; i++)
                #pragma unroll
                for (int j = 0; j < 8; j++) acc[i][j] += ar[i] * br[j];
        }
        __syncthreads();
    }
    #pragma unroll
    for (int ii = 0; ii < 2; ii++)
        #pragma unroll
        for (int i = 0; i < 4; i++) {
            int row = bm + ii*64 + ty*4 + i;
            #pragma unroll
            for (int jj = 0; jj < 2; jj++) {
                int col = bn + jj*64 + tx*4;
                float4 v = make_float4(acc[ii*4+i][jj*4+0], acc[ii*4+i][jj*4+1],
                                       acc[ii*4+i][jj*4+2], acc[ii*4+i][jj*4+3]);
                if (BIAS) {
                    v.x += bias[col];   v.y += bias[col+1];
                    v.z += bias[col+2]; v.w += bias[col+3];
                }
                *(float4*)&C[(size_t)row * N + col] = v;
            }
        }
}

// ---------------- persistent recurrence ----------------
__global__ void reset_bar_kernel() { g_barcnt = 0u; }

// Fence-free grid barrier: release-reduction + acquire poll (no L1D flush).
__device__ __forceinline__ void gbar(unsigned target) {
    __syncthreads();
    if (threadIdx.x == 0) {
        asm volatile("red.release.gpu.global.add.u32 [%0], %1;"
                     :: "l"(&g_barcnt), "r"(1u) : "memory");
        unsigned v;
        do {
            asm volatile("ld.acquire.gpu.global.u32 %0, [%1];"
                         : "=r"(v) : "l"(&g_barcnt) : "memory");
        } while (v < target);
    }
    __syncthreads();
}

// dyn smem layout (floats):
//   [0, 16384)      s_stage : phase A = h[b][k] flat ; phase B = m_t[k][b] flat
//   aliased after compute-B sync:
//     [0, 4608)     part[(ci*16+b)*9 + ks]
//     [8192, 8704)  zz[b*32 + ci]
//   [16384, 16640)  redA[256]
#define SM_STAGE 0
#define SM_PART  0
#define SM_ZZ    8192
#define SM_RED   16384
#define SM_FLOATS (16384 + 256)

__global__ void __launch_bounds__(256) recur_kernel(
    const float* __restrict__ zx, const float* __restrict__ mxp,
    const float* __restrict__ wmhnT, const float* __restrict__ whnT,
    float* __restrict__ hs)
{
    extern __shared__ float sm[];
    const int bk = blockIdx.x, tid = threadIdx.x;

    if (tid < 128) d_h[bk*128 + tid] = 0.f;
    unsigned tgt = NBLK;
    gbar(tgt); tgt += NBLK;

    // phase A mapping
    const int outA = tid >> 1, halfA = tid & 1;
    const int bA = outA >> 3, j0A = outA & 7;
    const int jA = bk*8 + j0A;
    // phase B mapping
    const int ksB = tid >> 5, ciB = tid & 31;
    const int qB = ciB >> 3, j0B = ciB & 7;
    const int colB = qB*H_ + bk*8 + j0B;
    // reduce-stage mapping (2 outputs per thread)
    int rci[2], rb[2]; size_t rzoff[2];
    #pragma unroll
    for (int o = 0; o < 2; o++) {
        int out = tid + o*256;
        rci[o] = out >> 4; rb[o] = out & 15;
        int q = rci[o] >> 3, j0 = rci[o] & 7;
        rzoff[o] = (size_t)rb[o]*T_*FH + (size_t)q*H_ + bk*8 + j0;
    }
    // gate-thread state
    const int bG = tid >> 3, j0G = tid & 7;
    float creg = 0.f;

    for (int t = 0; t < T_; t++) {
        // prefetch step inputs early (overlap L2/DRAM latency with compute)
        float zpre0 = __ldg(&zx[rzoff[0] + (size_t)t*FH]);
        float zpre1 = __ldg(&zx[rzoff[1] + (size_t)t*FH]);
        float mxv = 0.f;
        if (halfA == 0) mxv = __ldg(&mxp[(size_t)(bA*T_ + t)*H_ + jA]);

        // ---- stage h into smem ----
        {
            float4* dst = (float4*)(sm + SM_STAGE);
            const float4* src = (const float4*)d_h;
            #pragma unroll
            for (int i = tid; i < 4096; i += 256) dst[i] = __ldcg(src + i);
        }
        __syncthreads();

        // ---- phase A: m[b,j] = (h @ wmh_n)[b,j] * mx[b,t,j] ----
        {
            const float4* hp = (const float4*)(sm + SM_STAGE + bA*H_ + halfA*512);
            const float4* wp = (const float4*)(wmhnT + (size_t)jA*H_ + halfA*512);
            float ax=0.f, ay=0.f, az=0.f, aw=0.f;
            #pragma unroll 8
            for (int i = 0; i < 128; i++) {
                float4 hv = hp[i];
                float4 wv = __ldg(wp + i);
                ax += hv.x*wv.x; ay += hv.y*wv.y;
                az += hv.z*wv.z; aw += hv.w*wv.w;
            }
            sm[SM_RED + tid] = (ax + ay) + (az + aw);
        }
        __syncthreads();
        if (halfA == 0) {
            float s = sm[SM_RED + tid] + sm[SM_RED + tid + 1];
            __stcg(&d_mt[jA*B_ + bA], s * mxv);
        }
        gbar(tgt); tgt += NBLK;

        // ---- stage m_t into smem ----
        {
            float4* dst = (float4*)(sm + SM_STAGE);
            const float4* src = (const float4*)d_mt;
            #pragma unroll
            for (int i = tid; i < 4096; i += 256) dst[i] = __ldcg(src + i);
        }
        __syncthreads();

        // ---- phase B: z = zx_t + m @ wh_n ----
        float acc[16];
        #pragma unroll
        for (int b = 0; b < 16; b++) acc[b] = 0.f;
        {
            const float4* wp = (const float4*)(whnT + (size_t)colB*H_ + ksB*128);
            const float* mp = sm + SM_STAGE + ksB*128*B_;
            #pragma unroll 4
            for (int k4 = 0; k4 < 32; k4++) {
                float4 wv = __ldg(wp + k4);
                #pragma unroll
                for (int u = 0; u < 4; u++) {
                    float wk = (u==0) ? wv.x : (u==1) ? wv.y : (u==2) ? wv.z : wv.w;
                    const float4* m4 = (const float4*)(mp + (k4*4 + u)*B_);
                    float4 m0 = m4[0], m1 = m4[1], m2 = m4[2], m3 = m4[3];
                    acc[0]  += m0.x*wk; acc[1]  += m0.y*wk; acc[2]  += m0.z*wk; acc[3]  += m0.w*wk;
                    acc[4]  += m1.x*wk; acc[5]  += m1.y*wk; acc[6]  += m1.z*wk; acc[7]  += m1.w*wk;
                    acc[8]  += m2.x*wk; acc[9]  += m2.y*wk; acc[10] += m2.z*wk; acc[11] += m2.w*wk;
                    acc[12] += m3.x*wk; acc[13] += m3.y*wk; acc[14] += m3.z*wk; acc[15] += m3.w*wk;
                }
            }
        }
        __syncthreads();
        #pragma unroll
        for (int b = 0; b < 16; b++)
            sm[SM_PART + (ciB*16 + b)*9 + ksB] = acc[b];
        __syncthreads();

        // ---- reduce over kslices + add zx ----
        {
            const float* p0 = sm + SM_PART + (rci[0]*16 + rb[0])*9;
            float s0 = ((p0[0]+p0[1]) + (p0[2]+p0[3])) + ((p0[4]+p0[5]) + (p0[6]+p0[7]));
            sm[SM_ZZ + rb[0]*32 + rci[0]] = zpre0 + s0;
            const float* p1 = sm + SM_PART + (rci[1]*16 + rb[1])*9;
            float s1 = ((p1[0]+p1[1]) + (p1[2]+p1[3])) + ((p1[4]+p1[5]) + (p1[6]+p1[7]));
            sm[SM_ZZ + rb[1]*32 + rci[1]] = zpre1 + s1;
        }
        __syncthreads();

        // ---- gates + state update (tid < 128) ----
        if (tid < 128) {
            float zi = sm[SM_ZZ + bG*32 +      j0G];
            float zf = sm[SM_ZZ + bG*32 +  8 + j0G];
            float zo = sm[SM_ZZ + bG*32 + 16 + j0G];
            float zu = sm[SM_ZZ + bG*32 + 24 + j0G];
            float ig = 1.f / (1.f + expf(-zi));
            float fg = 1.f / (1.f + expf(-zf));
            float og = 1.f / (1.f + expf(-zo));
            float ug = tanhf(zu);
            creg = fg * creg + ig * ug;
            float h = og * tanhf(creg);
            int col = bk*8 + j0G;
            __stcg(&d_h[bG*H_ + col], h);
            hs[(size_t)(bG*T_ + t)*H_ + col] = h;
        }
        gbar(tgt); tgt += NBLK;
    }
}

// ---------------- single-pass online log-softmax NLL ----------------
__global__ void nll_kernel(const float* __restrict__ logits, const int* __restrict__ ys,
                           float* __restrict__ rownll) {
    __shared__ float smx[256], ssm[256];
    int row = blockIdx.x, tid = threadIdx.x;
    const float* l = logits + (size_t)row * V_;
    float m = -3.4e38f, s = 0.f;
    for (int v = tid; v < V_; v += 256) {
        float x = l[v];
        float nm = fmaxf(m, x);
        s = s * expf(m - nm) + expf(x - nm);
        m = nm;
    }
    smx[tid] = m; ssm[tid] = s; __syncthreads();
    for (int k = 128; k > 0; k >>= 1) {
        if (tid < k) {
            float m2 = smx[tid + k], s2 = ssm[tid + k];
            float M = fmaxf(smx[tid], m2);
            ssm[tid] = ssm[tid] * expf(smx[tid] - M) + s2 * expf(m2 - M);
            smx[tid] = M;
        }
        __syncthreads();
    }
    if (tid == 0)
        rownll[row] = -(l[ys[row]] - smx[0] - logf(ssm[0]));
}

__global__ void mean_kernel(const float* __restrict__ rownll, float* __restrict__ out) {
    __shared__ float sred[256];
    int tid = threadIdx.x;
    float s = 0.f;
    for (int i = tid; i < B_*T_; i += 256) s += rownll[i];
    sred[tid] = s; __syncthreads();
    for (int k = 128; k > 0; k >>= 1) {
        if (tid < k) sred[tid] += sred[tid + k];
        __syncthreads();
    }
    if (tid == 0) out[0] = sred[0] / (float)(B_*T_);
}

// ---------------- launcher ----------------
extern "C" void kernel_launch(void* const* d_in, const int* in_sizes, int n_in,
                              void* d_out, int out_size) {
    (void)in_sizes; (void)n_in; (void)out_size;
    const int*   xs      = (const int*)  d_in[0];
    const int*   ys      = (const int*)  d_in[1];
    const float* embed_w = (const float*)d_in[2];
    const float* wx      = (const float*)d_in[3];
    const float* wh      = (const float*)d_in[4];
    const float* wmx     = (const float*)d_in[5];
    const float* wmh     = (const float*)d_in[6];
    const float* bb      = (const float*)d_in[7];
    const float* gx      = (const float*)d_in[8];
    const float* gh      = (const float*)d_in[9];
    const float* gmx     = (const float*)d_in[10];
    const float* gmh     = (const float*)d_in[11];
    const float* pred_w  = (const float*)d_in[12];
    const float* pred_b  = (const float*)d_in[13];
    float* out = (float*)d_out;

    float *p_x, *p_wxn, *p_whnT, *p_wmxn, *p_wmhnT, *p_zx, *p_mx, *p_hs, *p_logits, *p_rownll;
    float *p_nwx, *p_nwh, *p_nwmx, *p_nwmh;
    cudaGetSymbolAddress((void**)&p_x,      d_x);
    cudaGetSymbolAddress((void**)&p_wxn,    d_wxn);
    cudaGetSymbolAddress((void**)&p_whnT,   d_whnT);
    cudaGetSymbolAddress((void**)&p_wmxn,   d_wmxn);
    cudaGetSymbolAddress((void**)&p_wmhnT,  d_wmhnT);
    cudaGetSymbolAddress((void**)&p_zx,     d_zx);
    cudaGetSymbolAddress((void**)&p_mx,     d_mx);
    cudaGetSymbolAddress((void**)&p_hs,     d_hs);
    cudaGetSymbolAddress((void**)&p_logits, d_logits);
    cudaGetSymbolAddress((void**)&p_rownll, d_rownll);
    cudaGetSymbolAddress((void**)&p_nwx,    d_nwx);
    cudaGetSymbolAddress((void**)&p_nwh,    d_nwh);
    cudaGetSymbolAddress((void**)&p_nwmx,   d_nwmx);
    cudaGetSymbolAddress((void**)&p_nwmh,   d_nwmh);

    static bool attr_set = false;
    if (!attr_set) {
        cudaFuncSetAttribute(recur_kernel, cudaFuncAttributeMaxDynamicSharedMemorySize,
                             SM_FLOATS * sizeof(float));
        attr_set = true;
    }

    // weight norm
    zero_norms_kernel<<<16, 256>>>();
    sumsq_kernel<<<dim3(FH/256, E_/128), 256>>>(wx,  p_nwx,  E_, FH);
    sumsq_kernel<<<dim3(FH/256, H_/128), 256>>>(wh,  p_nwh,  H_, FH);
    sumsq_kernel<<<dim3(H_/256, E_/128), 256>>>(wmx, p_nwmx, E_, H_);
    sumsq_kernel<<<dim3(H_/256, H_/128), 256>>>(wmh, p_nwmh, H_, H_);
    scale_plain_kernel<<<(E_*FH)/256, 256>>>(wx,  gx,  p_nwx,  p_wxn,  FH, E_*FH);
    scale_plain_kernel<<<(E_*H_)/256, 256>>>(wmx, gmx, p_nwmx, p_wmxn, H_, E_*H_);
    scaleT_kernel<<<dim3(FH/32, H_/32), dim3(32,8)>>>(wh,  gh,  p_nwh,  p_whnT,  H_, FH);
    scaleT_kernel<<<dim3(H_/32, H_/32), dim3(32,8)>>>(wmh, gmh, p_nwmh, p_wmhnT, H_, H_);

    // embedding
    embed_kernel<<<B_*T_, 128>>>(xs, embed_w, p_x);

    // input-dependent projections
    gemm128<false, true ><<<dim3(FH/128, (B_*T_)/128), 256>>>(p_x, p_wxn,  bb, p_zx, B_*T_, FH, E_);
    gemm128<false, false><<<dim3(H_/128, (B_*T_)/128), 256>>>(p_x, p_wmxn, (const float*)nullptr, p_mx, B_*T_, H_, E_);

    // recurrence
    reset_bar_kernel<<<1, 1>>>();
    recur_kernel<<<NBLK, 256, SM_FLOATS * sizeof(float)>>>(p_zx, p_mx, p_wmhnT, p_whnT, p_hs);

    // logits + loss
    gemm128<true, true><<<dim3(V_/128, (B_*T_)/128), 256>>>(p_hs, pred_w, pred_b, p_logits, B_*T_, V_, H_);
    nll_kernel<<<B_*T_, 256>>>(p_logits, ys, p_rownll);
    mean_kernel<<<1, 256>>>(p_rownll, out);
}

// round 5
// speedup vs baseline: 4.0361x; 1.0316x over previous
#include <cuda_runtime.h>
#include <cuda_bf16.h>
#include <cstdint>

#define B_  16
#define T_  512
#define V_  8192
#define E_  512
#define H_  1024
#define FH  4096
#define NBLK 128

// ---------------- device scratch ----------------
__device__ __nv_bfloat16 d_xhi[B_*T_*E_], d_xlo[B_*T_*E_];
__device__ __nv_bfloat16 d_wxnThi[(size_t)FH*E_], d_wxnTlo[(size_t)FH*E_];   // [4H][E]
__device__ __nv_bfloat16 d_wmxnThi[H_*E_], d_wmxnTlo[H_*E_];                 // [H][E]
__device__ __nv_bfloat16 d_pwhi[(size_t)V_*H_], d_pwlo[(size_t)V_*H_];       // [V][H]
__device__ __nv_bfloat16 d_hshi[B_*T_*H_], d_hslo[B_*T_*H_];                 // [B*T][H]
__device__ float d_whnT[(size_t)FH*H_];      // fp32, recurrence phase B
__device__ float d_wmhnT[H_*H_];             // fp32, recurrence phase A
__device__ float d_nwx[FH], d_nwh[FH], d_nwmx[H_], d_nwmh[H_];
__device__ float d_zx[(size_t)B_*T_*FH];
__device__ float d_mx[B_*T_*H_];
__device__ float d_h[B_*H_];
__device__ float d_mt[H_*B_];
__device__ float d_logits[(size_t)B_*T_*V_];
__device__ float d_rownll[B_*T_];
__device__ unsigned g_barcnt;

// ---------------- helpers ----------------
__device__ __forceinline__ uint32_t smem_u32(const void* p) {
    uint32_t a;
    asm("{ .reg .u64 t; cvta.to.shared.u64 t, %1; cvt.u32.u64 %0, t; }" : "=r"(a) : "l"(p));
    return a;
}
__device__ __forceinline__ void ldm_x4(uint32_t* r, uint32_t addr) {
    asm volatile("ldmatrix.sync.aligned.m8n8.x4.shared.b16 {%0,%1,%2,%3}, [%4];"
                 : "=r"(r[0]), "=r"(r[1]), "=r"(r[2]), "=r"(r[3]) : "r"(addr));
}
__device__ __forceinline__ void ldm_x2(uint32_t* r, uint32_t addr) {
    asm volatile("ldmatrix.sync.aligned.m8n8.x2.shared.b16 {%0,%1}, [%2];"
                 : "=r"(r[0]), "=r"(r[1]) : "r"(addr));
}
__device__ __forceinline__ void mma_bf16(float* c, const uint32_t* a, const uint32_t* b) {
    asm volatile("mma.sync.aligned.m16n8k16.row.col.f32.bf16.bf16.f32 "
                 "{%0,%1,%2,%3}, {%4,%5,%6,%7}, {%8,%9}, {%0,%1,%2,%3};"
                 : "+f"(c[0]), "+f"(c[1]), "+f"(c[2]), "+f"(c[3])
                 : "r"(a[0]), "r"(a[1]), "r"(a[2]), "r"(a[3]), "r"(b[0]), "r"(b[1]));
}

// ---------------- weight norm ----------------
__global__ void zero_norms_kernel() {
    int i = blockIdx.x * 256 + threadIdx.x;
    if (i < FH) { d_nwx[i] = 0.f; d_nwh[i] = 0.f; }
    if (i < H_) { d_nwmx[i] = 0.f; d_nwmh[i] = 0.f; }
}
__global__ void sumsq_kernel(const float* __restrict__ w, float* __restrict__ nrm,
                             int K, int N) {
    int j = blockIdx.x * 256 + threadIdx.x;
    int k0 = blockIdx.y * 128;
    float ss = 0.f;
    #pragma unroll 4
    for (int k = k0; k < k0 + 128; k++) { float v = w[(size_t)k*N + j]; ss += v*v; }
    atomicAdd(&nrm[j], ss);
}
__global__ void scaleT_kernel(const float* __restrict__ w, const float* __restrict__ g,
                              const float* __restrict__ nrm, float* __restrict__ out,
                              int K, int N) {
    __shared__ float tile[32][33];
    int n0 = blockIdx.x * 32, k0 = blockIdx.y * 32;
    int tx = threadIdx.x, ty = threadIdx.y;
    for (int r = ty; r < 32; r += 8)
        tile[r][tx] = w[(size_t)(k0 + r)*N + n0 + tx];
    __syncthreads();
    for (int r = ty; r < 32; r += 8) {
        int n = n0 + r;
        float s = g[n] / fmaxf(sqrtf(nrm[n]), 1e-12f);
        out[(size_t)n*K + k0 + tx] = tile[tx][r] * s;
    }
}
__global__ void scaleT_bf16_kernel(const float* __restrict__ w, const float* __restrict__ g,
                                   const float* __restrict__ nrm,
                                   __nv_bfloat16* __restrict__ ohi,
                                   __nv_bfloat16* __restrict__ olo,
                                   int K, int N) {
    __shared__ float tile[32][33];
    int n0 = blockIdx.x * 32, k0 = blockIdx.y * 32;
    int tx = threadIdx.x, ty = threadIdx.y;
    for (int r = ty; r < 32; r += 8)
        tile[r][tx] = w[(size_t)(k0 + r)*N + n0 + tx];
    __syncthreads();
    for (int r = ty; r < 32; r += 8) {
        int n = n0 + r;
        float s = g[n] / fmaxf(sqrtf(nrm[n]), 1e-12f);
        float v = tile[tx][r] * s;
        __nv_bfloat16 hi = __float2bfloat16(v);
        ohi[(size_t)n*K + k0 + tx] = hi;
        olo[(size_t)n*K + k0 + tx] = __float2bfloat16(v - __bfloat162float(hi));
    }
}
__global__ void split_kernel(const float* __restrict__ w,
                             __nv_bfloat16* __restrict__ ohi,
                             __nv_bfloat16* __restrict__ olo, size_t total) {
    size_t i = (size_t)blockIdx.x * 256 + threadIdx.x;
    if (i >= total) return;
    float v = w[i];
    __nv_bfloat16 hi = __float2bfloat16(v);
    ohi[i] = hi;
    olo[i] = __float2bfloat16(v - __bfloat162float(hi));
}

// ---------------- embedding, padding_idx = 0, bf16 split output ----------------
__global__ void embed_kernel(const int* __restrict__ xs, const float* __restrict__ ew,
                             __nv_bfloat16* __restrict__ xhi, __nv_bfloat16* __restrict__ xlo) {
    int r = blockIdx.x;
    int idx = xs[r];
    const float4* src = (const float4*)(ew + (size_t)idx * E_);
    float4 v = src[threadIdx.x];
    if (idx == 0) v = make_float4(0.f, 0.f, 0.f, 0.f);
    size_t base = (size_t)r * E_ + threadIdx.x * 4;
    float vv[4] = {v.x, v.y, v.z, v.w};
    #pragma unroll
    for (int u = 0; u < 4; u++) {
        __nv_bfloat16 hi = __float2bfloat16(vv[u]);
        xhi[base + u] = hi;
        xlo[base + u] = __float2bfloat16(vv[u] - __bfloat162float(hi));
    }
}

// ---------------- mma.sync split-bf16 GEMM ----------------
// C[M,N] = A[M,K] * B[N,K]^T (+bias). A/B are (hi,lo) bf16 pairs; fp32 accum.
// 128x128 CTA tile, BK=64; 8 warps in 2(m) x 4(n), warp tile 64x32.
// smem: 4 tiles of 16KB (Ahi, Alo, Bhi, Blo), 16B-chunk swizzle c^(row&7).
#define GSMEM 65536

template<bool BIAS>
__global__ void __launch_bounds__(256) mma_gemm(
    const __nv_bfloat16* __restrict__ Ahi, const __nv_bfloat16* __restrict__ Alo,
    const __nv_bfloat16* __restrict__ Bhi, const __nv_bfloat16* __restrict__ Blo,
    const float* __restrict__ bias, float* __restrict__ C,
    int M, int N, int K)
{
    extern __shared__ char smem[];
    const uint32_t sbase = smem_u32(smem);
    const int tid = threadIdx.x, lid = tid & 31, wid = tid >> 5;
    const int wm = (wid & 1) * 64, wn = (wid >> 1) * 32;
    const int bn = blockIdx.x * 128, bm = blockIdx.y * 128;

    float acc[4][4][4];
    #pragma unroll
    for (int mt = 0; mt < 4; mt++)
        #pragma unroll
        for (int nt = 0; nt < 4; nt++)
            #pragma unroll
            for (int u = 0; u < 4; u++) acc[mt][nt][u] = 0.f;

    // per-thread load indices (16 x 16B per thread per chunk)
    for (int k0 = 0; k0 < K; k0 += 64) {
        #pragma unroll
        for (int p = 0; p < 16; p++) {
            int i = tid + p * 256;
            int tile = i >> 10, j = i & 1023;
            int row = j >> 3, c = j & 7;
            const __nv_bfloat16* src = (tile == 0) ? Ahi : (tile == 1) ? Alo
                                     : (tile == 2) ? Bhi : Blo;
            int grow = ((tile < 2) ? bm : bn) + row;
            uint4 v = *(const uint4*)(src + (size_t)grow * K + k0 + c * 8);
            *(uint4*)(smem + tile * 16384 + (row * 8 + (c ^ (row & 7))) * 16) = v;
        }
        __syncthreads();
        #pragma unroll
        for (int ks = 0; ks < 4; ks++) {
            // B fragments (hi, lo) for 4 n-tiles
            uint32_t bh[4][2], bl[4][2];
            {
                int row = wn + (lid & 7);
                int cc = 2 * ks + ((lid >> 3) & 1);
                #pragma unroll
                for (int nt = 0; nt < 4; nt++) {
                    int r = row + nt * 8;
                    uint32_t addr = sbase + 32768 + (r * 8 + (cc ^ (r & 7))) * 16;
                    ldm_x2(bh[nt], addr);
                    ldm_x2(bl[nt], addr + 16384);
                }
            }
            #pragma unroll
            for (int mt = 0; mt < 4; mt++) {
                int r = wm + mt * 16 + (lid & 7) + ((lid >> 3) & 1) * 8;
                int cc = 2 * ks + (lid >> 4);
                uint32_t addr = sbase + (r * 8 + (cc ^ (r & 7))) * 16;
                uint32_t ah[4], al[4];
                ldm_x4(ah, addr);
                ldm_x4(al, addr + 16384);
                #pragma unroll
                for (int nt = 0; nt < 4; nt++) {
                    mma_bf16(acc[mt][nt], ah, bh[nt]);
                    mma_bf16(acc[mt][nt], ah, bl[nt]);
                    mma_bf16(acc[mt][nt], al, bh[nt]);
                }
            }
        }
        __syncthreads();
    }

    // epilogue: registers -> global (+bias)
    const int mrow = (lid >> 2), ncol = (lid & 3) * 2;
    #pragma unroll
    for (int mt = 0; mt < 4; mt++) {
        #pragma unroll
        for (int nt = 0; nt < 4; nt++) {
            int row0 = bm + wm + mt * 16 + mrow;
            int col = bn + wn + nt * 8 + ncol;
            float2 v0 = make_float2(acc[mt][nt][0], acc[mt][nt][1]);
            float2 v1 = make_float2(acc[mt][nt][2], acc[mt][nt][3]);
            if (BIAS) {
                float b0 = bias[col], b1 = bias[col + 1];
                v0.x += b0; v0.y += b1;
                v1.x += b0; v1.y += b1;
            }
            *(float2*)&C[(size_t)row0 * N + col] = v0;
            *(float2*)&C[(size_t)(row0 + 8) * N + col] = v1;
        }
    }
}

// ---------------- persistent recurrence (unchanged from R3) ----------------
__global__ void reset_bar_kernel() { g_barcnt = 0u; }

__device__ __forceinline__ void gbar(unsigned target) {
    __syncthreads();
    if (threadIdx.x == 0) {
        asm volatile("red.release.gpu.global.add.u32 [%0], %1;"
                     :: "l"(&g_barcnt), "r"(1u) : "memory");
        unsigned v;
        do {
            asm volatile("ld.acquire.gpu.global.u32 %0, [%1];"
                         : "=r"(v) : "l"(&g_barcnt) : "memory");
        } while (v < target);
    }
    __syncthreads();
}

#define SM_STAGE 0
#define SM_PART  0
#define SM_ZZ    8192
#define SM_RED   16384
#define SM_FLOATS (16384 + 256)

__global__ void __launch_bounds__(256) recur_kernel(
    const float* __restrict__ zx, const float* __restrict__ mxp,
    const float* __restrict__ wmhnT, const float* __restrict__ whnT,
    __nv_bfloat16* __restrict__ hshi, __nv_bfloat16* __restrict__ hslo)
{
    extern __shared__ float sm[];
    const int bk = blockIdx.x, tid = threadIdx.x;

    if (tid < 128) d_h[bk*128 + tid] = 0.f;
    unsigned tgt = NBLK;
    gbar(tgt); tgt += NBLK;

    const int outA = tid >> 1, halfA = tid & 1;
    const int bA = outA >> 3, j0A = outA & 7;
    const int jA = bk*8 + j0A;
    const int ksB = tid >> 5, ciB = tid & 31;
    const int qB = ciB >> 3, j0B = ciB & 7;
    const int colB = qB*H_ + bk*8 + j0B;
    int rci[2], rb[2]; size_t rzoff[2];
    #pragma unroll
    for (int o = 0; o < 2; o++) {
        int out = tid + o*256;
        rci[o] = out >> 4; rb[o] = out & 15;
        int q = rci[o] >> 3, j0 = rci[o] & 7;
        rzoff[o] = (size_t)rb[o]*T_*FH + (size_t)q*H_ + bk*8 + j0;
    }
    const int bG = tid >> 3, j0G = tid & 7;
    float creg = 0.f;

    for (int t = 0; t < T_; t++) {
        float zpre0 = __ldg(&zx[rzoff[0] + (size_t)t*FH]);
        float zpre1 = __ldg(&zx[rzoff[1] + (size_t)t*FH]);
        float mxv = 0.f;
        if (halfA == 0) mxv = __ldg(&mxp[(size_t)(bA*T_ + t)*H_ + jA]);

        {   // stage h
            float4* dst = (float4*)(sm + SM_STAGE);
            const float4* src = (const float4*)d_h;
            #pragma unroll
            for (int i = tid; i < 4096; i += 256) dst[i] = __ldcg(src + i);
        }
        __syncthreads();

        {   // phase A
            const float4* hp = (const float4*)(sm + SM_STAGE + bA*H_ + halfA*512);
            const float4* wp = (const float4*)(wmhnT + (size_t)jA*H_ + halfA*512);
            float ax=0.f, ay=0.f, az=0.f, aw=0.f;
            #pragma unroll 8
            for (int i = 0; i < 128; i++) {
                float4 hv = hp[i];
                float4 wv = __ldg(wp + i);
                ax += hv.x*wv.x; ay += hv.y*wv.y;
                az += hv.z*wv.z; aw += hv.w*wv.w;
            }
            sm[SM_RED + tid] = (ax + ay) + (az + aw);
        }
        __syncthreads();
        if (halfA == 0) {
            float s = sm[SM_RED + tid] + sm[SM_RED + tid + 1];
            __stcg(&d_mt[jA*B_ + bA], s * mxv);
        }
        gbar(tgt); tgt += NBLK;

        {   // stage m_t
            float4* dst = (float4*)(sm + SM_STAGE);
            const float4* src = (const float4*)d_mt;
            #pragma unroll
            for (int i = tid; i < 4096; i += 256) dst[i] = __ldcg(src + i);
        }
        __syncthreads();

        // phase B
        float acc[16];
        #pragma unroll
        for (int b = 0; b < 16; b++) acc[b] = 0.f;
        {
            const float4* wp = (const float4*)(whnT + (size_t)colB*H_ + ksB*128);
            const float* mp = sm + SM_STAGE + ksB*128*B_;
            #pragma unroll 4
            for (int k4 = 0; k4 < 32; k4++) {
                float4 wv = __ldg(wp + k4);
                #pragma unroll
                for (int u = 0; u < 4; u++) {
                    float wk = (u==0) ? wv.x : (u==1) ? wv.y : (u==2) ? wv.z : wv.w;
                    const float4* m4 = (const float4*)(mp + (k4*4 + u)*B_);
                    float4 m0 = m4[0], m1 = m4[1], m2 = m4[2], m3 = m4[3];
                    acc[0]  += m0.x*wk; acc[1]  += m0.y*wk; acc[2]  += m0.z*wk; acc[3]  += m0.w*wk;
                    acc[4]  += m1.x*wk; acc[5]  += m1.y*wk; acc[6]  += m1.z*wk; acc[7]  += m1.w*wk;
                    acc[8]  += m2.x*wk; acc[9]  += m2.y*wk; acc[10] += m2.z*wk; acc[11] += m2.w*wk;
                    acc[12] += m3.x*wk; acc[13] += m3.y*wk; acc[14] += m3.z*wk; acc[15] += m3.w*wk;
                }
            }
        }
        __syncthreads();
        #pragma unroll
        for (int b = 0; b < 16; b++)
            sm[SM_PART + (ciB*16 + b)*9 + ksB] = acc[b];
        __syncthreads();

        {
            const float* p0 = sm + SM_PART + (rci[0]*16 + rb[0])*9;
            float s0 = ((p0[0]+p0[1]) + (p0[2]+p0[3])) + ((p0[4]+p0[5]) + (p0[6]+p0[7]));
            sm[SM_ZZ + rb[0]*32 + rci[0]] = zpre0 + s0;
            const float* p1 = sm + SM_PART + (rci[1]*16 + rb[1])*9;
            float s1 = ((p1[0]+p1[1]) + (p1[2]+p1[3])) + ((p1[4]+p1[5]) + (p1[6]+p1[7]));
            sm[SM_ZZ + rb[1]*32 + rci[1]] = zpre1 + s1;
        }
        __syncthreads();

        if (tid < 128) {
            float zi = sm[SM_ZZ + bG*32 +      j0G];
            float zf = sm[SM_ZZ + bG*32 +  8 + j0G];
            float zo = sm[SM_ZZ + bG*32 + 16 + j0G];
            float zu = sm[SM_ZZ + bG*32 + 24 + j0G];
            float ig = 1.f / (1.f + expf(-zi));
            float fg = 1.f / (1.f + expf(-zf));
            float og = 1.f / (1.f + expf(-zo));
            float ug = tanhf(zu);
            creg = fg * creg + ig * ug;
            float h = og * tanhf(creg);
            int col = bk*8 + j0G;
            __stcg(&d_h[bG*H_ + col], h);
            size_t hidx = (size_t)(bG*T_ + t)*H_ + col;
            __nv_bfloat16 hh = __float2bfloat16(h);
            hshi[hidx] = hh;
            hslo[hidx] = __float2bfloat16(h - __bfloat162float(hh));
        }
        gbar(tgt); tgt += NBLK;
    }
}

// ---------------- single-pass online log-softmax NLL ----------------
__global__ void nll_kernel(const float* __restrict__ logits, const int* __restrict__ ys,
                           float* __restrict__ rownll) {
    __shared__ float smx[256], ssm[256];
    int row = blockIdx.x, tid = threadIdx.x;
    const float* l = logits + (size_t)row * V_;
    float m = -3.4e38f, s = 0.f;
    for (int v = tid; v < V_; v += 256) {
        float x = l[v];
        float nm = fmaxf(m, x);
        s = s * expf(m - nm) + expf(x - nm);
        m = nm;
    }
    smx[tid] = m; ssm[tid] = s; __syncthreads();
    for (int k = 128; k > 0; k >>= 1) {
        if (tid < k) {
            float m2 = smx[tid + k], s2 = ssm[tid + k];
            float M = fmaxf(smx[tid], m2);
            ssm[tid] = ssm[tid] * expf(smx[tid] - M) + s2 * expf(m2 - M);
            smx[tid] = M;
        }
        __syncthreads();
    }
    if (tid == 0)
        rownll[row] = -(l[ys[row]] - smx[0] - logf(ssm[0]));
}

__global__ void mean_kernel(const float* __restrict__ rownll, float* __restrict__ out) {
    __shared__ float sred[256];
    int tid = threadIdx.x;
    float s = 0.f;
    for (int i = tid; i < B_*T_; i += 256) s += rownll[i];
    sred[tid] = s; __syncthreads();
    for (int k = 128; k > 0; k >>= 1) {
        if (tid < k) sred[tid] += sred[tid + k];
        __syncthreads();
    }
    if (tid == 0) out[0] = sred[0] / (float)(B_*T_);
}

// ---------------- launcher ----------------
extern "C" void kernel_launch(void* const* d_in, const int* in_sizes, int n_in,
                              void* d_out, int out_size) {
    (void)in_sizes; (void)n_in; (void)out_size;
    const int*   xs      = (const int*)  d_in[0];
    const int*   ys      = (const int*)  d_in[1];
    const float* embed_w = (const float*)d_in[2];
    const float* wx      = (const float*)d_in[3];
    const float* wh      = (const float*)d_in[4];
    const float* wmx     = (const float*)d_in[5];
    const float* wmh     = (const float*)d_in[6];
    const float* bb      = (const float*)d_in[7];
    const float* gx      = (const float*)d_in[8];
    const float* gh      = (const float*)d_in[9];
    const float* gmx     = (const float*)d_in[10];
    const float* gmh     = (const float*)d_in[11];
    const float* pred_w  = (const float*)d_in[12];
    const float* pred_b  = (const float*)d_in[13];
    float* out = (float*)d_out;

    float *p_whnT, *p_wmhnT, *p_zx, *p_mx, *p_logits, *p_rownll;
    float *p_nwx, *p_nwh, *p_nwmx, *p_nwmh;
    __nv_bfloat16 *p_xhi, *p_xlo, *p_wxnThi, *p_wxnTlo, *p_wmxnThi, *p_wmxnTlo;
    __nv_bfloat16 *p_pwhi, *p_pwlo, *p_hshi, *p_hslo;
    cudaGetSymbolAddress((void**)&p_whnT,    d_whnT);
    cudaGetSymbolAddress((void**)&p_wmhnT,   d_wmhnT);
    cudaGetSymbolAddress((void**)&p_zx,      d_zx);
    cudaGetSymbolAddress((void**)&p_mx,      d_mx);
    cudaGetSymbolAddress((void**)&p_logits,  d_logits);
    cudaGetSymbolAddress((void**)&p_rownll,  d_rownll);
    cudaGetSymbolAddress((void**)&p_nwx,     d_nwx);
    cudaGetSymbolAddress((void**)&p_nwh,     d_nwh);
    cudaGetSymbolAddress((void**)&p_nwmx,    d_nwmx);
    cudaGetSymbolAddress((void**)&p_nwmh,    d_nwmh);
    cudaGetSymbolAddress((void**)&p_xhi,     d_xhi);
    cudaGetSymbolAddress((void**)&p_xlo,     d_xlo);
    cudaGetSymbolAddress((void**)&p_wxnThi,  d_wxnThi);
    cudaGetSymbolAddress((void**)&p_wxnTlo,  d_wxnTlo);
    cudaGetSymbolAddress((void**)&p_wmxnThi, d_wmxnThi);
    cudaGetSymbolAddress((void**)&p_wmxnTlo, d_wmxnTlo);
    cudaGetSymbolAddress((void**)&p_pwhi,    d_pwhi);
    cudaGetSymbolAddress((void**)&p_pwlo,    d_pwlo);
    cudaGetSymbolAddress((void**)&p_hshi,    d_hshi);
    cudaGetSymbolAddress((void**)&p_hslo,    d_hslo);

    static bool attr_set = false;
    if (!attr_set) {
        cudaFuncSetAttribute(recur_kernel, cudaFuncAttributeMaxDynamicSharedMemorySize,
                             SM_FLOATS * sizeof(float));
        cudaFuncSetAttribute(mma_gemm<true>,  cudaFuncAttributeMaxDynamicSharedMemorySize, GSMEM);
        cudaFuncSetAttribute(mma_gemm<false>, cudaFuncAttributeMaxDynamicSharedMemorySize, GSMEM);
        attr_set = true;
    }

    // weight norm
    zero_norms_kernel<<<16, 256>>>();
    sumsq_kernel<<<dim3(FH/256, E_/128), 256>>>(wx,  p_nwx,  E_, FH);
    sumsq_kernel<<<dim3(FH/256, H_/128), 256>>>(wh,  p_nwh,  H_, FH);
    sumsq_kernel<<<dim3(H_/256, E_/128), 256>>>(wmx, p_nwmx, E_, H_);
    sumsq_kernel<<<dim3(H_/256, H_/128), 256>>>(wmh, p_nwmh, H_, H_);
    scaleT_bf16_kernel<<<dim3(FH/32, E_/32), dim3(32,8)>>>(wx,  gx,  p_nwx,  p_wxnThi,  p_wxnTlo,  E_, FH);
    scaleT_bf16_kernel<<<dim3(H_/32, E_/32), dim3(32,8)>>>(wmx, gmx, p_nwmx, p_wmxnThi, p_wmxnTlo, E_, H_);
    scaleT_kernel<<<dim3(FH/32, H_/32), dim3(32,8)>>>(wh,  gh,  p_nwh,  p_whnT,  H_, FH);
    scaleT_kernel<<<dim3(H_/32, H_/32), dim3(32,8)>>>(wmh, gmh, p_nwmh, p_wmhnT, H_, H_);
    split_kernel<<<(int)(((size_t)V_*H_ + 255)/256), 256>>>(pred_w, p_pwhi, p_pwlo, (size_t)V_*H_);

    // embedding (bf16 split)
    embed_kernel<<<B_*T_, 128>>>(xs, embed_w, p_xhi, p_xlo);

    // input projections on tensor cores (mma.sync)
    mma_gemm<true ><<<dim3(FH/128, (B_*T_)/128), 256, GSMEM>>>(
        p_xhi, p_xlo, p_wxnThi, p_wxnTlo, bb, p_zx, B_*T_, FH, E_);
    mma_gemm<false><<<dim3(H_/128, (B_*T_)/128), 256, GSMEM>>>(
        p_xhi, p_xlo, p_wmxnThi, p_wmxnTlo, (const float*)nullptr, p_mx, B_*T_, H_, E_);

    // recurrence
    reset_bar_kernel<<<1, 1>>>();
    recur_kernel<<<NBLK, 256, SM_FLOATS * sizeof(float)>>>(
        p_zx, p_mx, p_wmhnT, p_whnT, p_hshi, p_hslo);

    // logits on tensor cores + loss
    mma_gemm<true><<<dim3(V_/128, (B_*T_)/128), 256, GSMEM>>>(
        p_hshi, p_hslo, p_pwhi, p_pwlo, pred_b, p_logits, B_*T_, V_, H_);
    nll_kernel<<<B_*T_, 256>>>(p_logits, ys, p_rownll);
    mean_kernel<<<1, 256>>>(p_rownll, out);
}

// round 6
// speedup vs baseline: 7.2191x; 1.7886x over previous
#include <cuda_runtime.h>
#include <cuda_bf16.h>
#include <cstdint>

#define B_  16
#define T_  512
#define V_  8192
#define E_  512
#define H_  1024
#define FH  4096
#define NBLK 128

// ---------------- device scratch ----------------
__device__ __nv_bfloat16 d_xhi[B_*T_*E_], d_xlo[B_*T_*E_];
__device__ __nv_bfloat16 d_wxnThi[(size_t)FH*E_], d_wxnTlo[(size_t)FH*E_];
__device__ __nv_bfloat16 d_wmxnThi[H_*E_], d_wmxnTlo[H_*E_];
__device__ __nv_bfloat16 d_pwhi[(size_t)V_*H_], d_pwlo[(size_t)V_*H_];
__device__ __nv_bfloat16 d_hshi[B_*T_*H_], d_hslo[B_*T_*H_];
__device__ float d_whnT[(size_t)FH*H_];      // [4096][1024]
__device__ float d_wmhnT[H_*H_];             // [1024][1024]
__device__ float d_nwx[FH], d_nwh[FH], d_nwmx[H_], d_nwmh[H_];
__device__ float d_zx[(size_t)B_*T_*FH];
__device__ float d_mx[B_*T_*H_];
__device__ float d_h[B_*H_];
__device__ float d_mt[H_*B_];
__device__ float d_logits[(size_t)B_*T_*V_];
__device__ float d_rownll[B_*T_];
__device__ unsigned g_barcnt;

// ---------------- helpers ----------------
__device__ __forceinline__ uint32_t smem_u32(const void* p) {
    uint32_t a;
    asm("{ .reg .u64 t; cvta.to.shared.u64 t, %1; cvt.u32.u64 %0, t; }" : "=r"(a) : "l"(p));
    return a;
}
__device__ __forceinline__ void ldm_x4(uint32_t* r, uint32_t addr) {
    asm volatile("ldmatrix.sync.aligned.m8n8.x4.shared.b16 {%0,%1,%2,%3}, [%4];"
                 : "=r"(r[0]), "=r"(r[1]), "=r"(r[2]), "=r"(r[3]) : "r"(addr));
}
__device__ __forceinline__ void ldm_x2(uint32_t* r, uint32_t addr) {
    asm volatile("ldmatrix.sync.aligned.m8n8.x2.shared.b16 {%0,%1}, [%2];"
                 : "=r"(r[0]), "=r"(r[1]) : "r"(addr));
}
__device__ __forceinline__ void mma_bf16(float* c, const uint32_t* a, const uint32_t* b) {
    asm volatile("mma.sync.aligned.m16n8k16.row.col.f32.bf16.bf16.f32 "
                 "{%0,%1,%2,%3}, {%4,%5,%6,%7}, {%8,%9}, {%0,%1,%2,%3};"
                 : "+f"(c[0]), "+f"(c[1]), "+f"(c[2]), "+f"(c[3])
                 : "r"(a[0]), "r"(a[1]), "r"(a[2]), "r"(a[3]), "r"(b[0]), "r"(b[1]));
}

// ---------------- weight norm ----------------
__global__ void zero_norms_kernel() {
    int i = blockIdx.x * 256 + threadIdx.x;
    if (i < FH) { d_nwx[i] = 0.f; d_nwh[i] = 0.f; }
    if (i < H_) { d_nwmx[i] = 0.f; d_nwmh[i] = 0.f; }
}
__global__ void sumsq_kernel(const float* __restrict__ w, float* __restrict__ nrm,
                             int K, int N) {
    int j = blockIdx.x * 256 + threadIdx.x;
    int k0 = blockIdx.y * 128;
    float ss = 0.f;
    #pragma unroll 4
    for (int k = k0; k < k0 + 128; k++) { float v = w[(size_t)k*N + j]; ss += v*v; }
    atomicAdd(&nrm[j], ss);
}
__global__ void scaleT_kernel(const float* __restrict__ w, const float* __restrict__ g,
                              const float* __restrict__ nrm, float* __restrict__ out,
                              int K, int N) {
    __shared__ float tile[32][33];
    int n0 = blockIdx.x * 32, k0 = blockIdx.y * 32;
    int tx = threadIdx.x, ty = threadIdx.y;
    for (int r = ty; r < 32; r += 8)
        tile[r][tx] = w[(size_t)(k0 + r)*N + n0 + tx];
    __syncthreads();
    for (int r = ty; r < 32; r += 8) {
        int n = n0 + r;
        float s = g[n] / fmaxf(sqrtf(nrm[n]), 1e-12f);
        out[(size_t)n*K + k0 + tx] = tile[tx][r] * s;
    }
}
__global__ void scaleT_bf16_kernel(const float* __restrict__ w, const float* __restrict__ g,
                                   const float* __restrict__ nrm,
                                   __nv_bfloat16* __restrict__ ohi,
                                   __nv_bfloat16* __restrict__ olo,
                                   int K, int N) {
    __shared__ float tile[32][33];
    int n0 = blockIdx.x * 32, k0 = blockIdx.y * 32;
    int tx = threadIdx.x, ty = threadIdx.y;
    for (int r = ty; r < 32; r += 8)
        tile[r][tx] = w[(size_t)(k0 + r)*N + n0 + tx];
    __syncthreads();
    for (int r = ty; r < 32; r += 8) {
        int n = n0 + r;
        float s = g[n] / fmaxf(sqrtf(nrm[n]), 1e-12f);
        float v = tile[tx][r] * s;
        __nv_bfloat16 hi = __float2bfloat16(v);
        ohi[(size_t)n*K + k0 + tx] = hi;
        olo[(size_t)n*K + k0 + tx] = __float2bfloat16(v - __bfloat162float(hi));
    }
}
__global__ void split_kernel(const float* __restrict__ w,
                             __nv_bfloat16* __restrict__ ohi,
                             __nv_bfloat16* __restrict__ olo, size_t total) {
    size_t i = (size_t)blockIdx.x * 256 + threadIdx.x;
    if (i >= total) return;
    float v = w[i];
    __nv_bfloat16 hi = __float2bfloat16(v);
    ohi[i] = hi;
    olo[i] = __float2bfloat16(v - __bfloat162float(hi));
}

// ---------------- embedding ----------------
__global__ void embed_kernel(const int* __restrict__ xs, const float* __restrict__ ew,
                             __nv_bfloat16* __restrict__ xhi, __nv_bfloat16* __restrict__ xlo) {
    int r = blockIdx.x;
    int idx = xs[r];
    const float4* src = (const float4*)(ew + (size_t)idx * E_);
    float4 v = src[threadIdx.x];
    if (idx == 0) v = make_float4(0.f, 0.f, 0.f, 0.f);
    size_t base = (size_t)r * E_ + threadIdx.x * 4;
    float vv[4] = {v.x, v.y, v.z, v.w};
    #pragma unroll
    for (int u = 0; u < 4; u++) {
        __nv_bfloat16 hi = __float2bfloat16(vv[u]);
        xhi[base + u] = hi;
        xlo[base + u] = __float2bfloat16(vv[u] - __bfloat162float(hi));
    }
}

// ---------------- mma.sync split-bf16 GEMM (unchanged from R5) ----------------
#define GSMEM 65536

template<bool BIAS>
__global__ void __launch_bounds__(256) mma_gemm(
    const __nv_bfloat16* __restrict__ Ahi, const __nv_bfloat16* __restrict__ Alo,
    const __nv_bfloat16* __restrict__ Bhi, const __nv_bfloat16* __restrict__ Blo,
    const float* __restrict__ bias, float* __restrict__ C,
    int M, int N, int K)
{
    extern __shared__ char smem[];
    const uint32_t sbase = smem_u32(smem);
    const int tid = threadIdx.x, lid = tid & 31, wid = tid >> 5;
    const int wm = (wid & 1) * 64, wn = (wid >> 1) * 32;
    const int bn = blockIdx.x * 128, bm = blockIdx.y * 128;

    float acc[4][4][4];
    #pragma unroll
    for (int mt = 0; mt < 4; mt++)
        #pragma unroll
        for (int nt = 0; nt < 4; nt++)
            #pragma unroll
            for (int u = 0; u < 4; u++) acc[mt][nt][u] = 0.f;

    for (int k0 = 0; k0 < K; k0 += 64) {
        #pragma unroll
        for (int p = 0; p < 16; p++) {
            int i = tid + p * 256;
            int tile = i >> 10, j = i & 1023;
            int row = j >> 3, c = j & 7;
            const __nv_bfloat16* src = (tile == 0) ? Ahi : (tile == 1) ? Alo
                                     : (tile == 2) ? Bhi : Blo;
            int grow = ((tile < 2) ? bm : bn) + row;
            uint4 v = *(const uint4*)(src + (size_t)grow * K + k0 + c * 8);
            *(uint4*)(smem + tile * 16384 + (row * 8 + (c ^ (row & 7))) * 16) = v;
        }
        __syncthreads();
        #pragma unroll
        for (int ks = 0; ks < 4; ks++) {
            uint32_t bh[4][2], bl[4][2];
            {
                int row = wn + (lid & 7);
                int cc = 2 * ks + ((lid >> 3) & 1);
                #pragma unroll
                for (int nt = 0; nt < 4; nt++) {
                    int r = row + nt * 8;
                    uint32_t addr = sbase + 32768 + (r * 8 + (cc ^ (r & 7))) * 16;
                    ldm_x2(bh[nt], addr);
                    ldm_x2(bl[nt], addr + 16384);
                }
            }
            #pragma unroll
            for (int mt = 0; mt < 4; mt++) {
                int r = wm + mt * 16 + (lid & 7) + ((lid >> 3) & 1) * 8;
                int cc = 2 * ks + (lid >> 4);
                uint32_t addr = sbase + (r * 8 + (cc ^ (r & 7))) * 16;
                uint32_t ah[4], al[4];
                ldm_x4(ah, addr);
                ldm_x4(al, addr + 16384);
                #pragma unroll
                for (int nt = 0; nt < 4; nt++) {
                    mma_bf16(acc[mt][nt], ah, bh[nt]);
                    mma_bf16(acc[mt][nt], ah, bl[nt]);
                    mma_bf16(acc[mt][nt], al, bh[nt]);
                }
            }
        }
        __syncthreads();
    }

    const int mrow = (lid >> 2), ncol = (lid & 3) * 2;
    #pragma unroll
    for (int mt = 0; mt < 4; mt++) {
        #pragma unroll
        for (int nt = 0; nt < 4; nt++) {
            int row0 = bm + wm + mt * 16 + mrow;
            int col = bn + wn + nt * 8 + ncol;
            float2 v0 = make_float2(acc[mt][nt][0], acc[mt][nt][1]);
            float2 v1 = make_float2(acc[mt][nt][2], acc[mt][nt][3]);
            if (BIAS) {
                float b0 = bias[col], b1 = bias[col + 1];
                v0.x += b0; v0.y += b1;
                v1.x += b0; v1.y += b1;
            }
            *(float2*)&C[(size_t)row0 * N + col] = v0;
            *(float2*)&C[(size_t)(row0 + 8) * N + col] = v1;
        }
    }
}

// ---------------- persistent recurrence: weights resident in SMEM ----------------
__global__ void reset_bar_kernel() { g_barcnt = 0u; }

__device__ __forceinline__ void gbar(unsigned target) {
    __syncthreads();
    if (threadIdx.x == 0) {
        asm volatile("red.release.gpu.global.add.u32 [%0], %1;"
                     :: "l"(&g_barcnt), "r"(1u) : "memory");
        unsigned v;
        do {
            asm volatile("ld.acquire.gpu.global.u32 %0, [%1];"
                         : "=r"(v) : "l"(&g_barcnt) : "memory");
        } while (v < target);
    }
    __syncthreads();
}

// dyn smem (bytes): wB4 131072 | wA4 32768 | stage 65536 | red 1024  = 230400
#define RS_WB    0               // float4[8192]   : [k4 256][ci 32] xor-swizzled
#define RS_WA    32768           // float  offset  : float4[2048] [k4 256][j 8] xor-swizzled
#define RS_STG   40960           // float  offset  : 16384 floats (h [b][k] / mt [k][b])
#define RS_RED   57344           // float  offset  : 256
#define RS_BYTES 230400

__global__ void __launch_bounds__(256) recur_kernel(
    const float* __restrict__ zx, const float* __restrict__ mxp,
    const float* __restrict__ wmhnT, const float* __restrict__ whnT,
    __nv_bfloat16* __restrict__ hshi, __nv_bfloat16* __restrict__ hslo)
{
    extern __shared__ float sm[];
    float4* wB4 = (float4*)sm;
    float4* wA4 = (float4*)(sm + RS_WA);
    float*  stg = sm + RS_STG;
    float*  red = sm + RS_RED;
    const int bk = blockIdx.x, tid = threadIdx.x;

    // ---- one-time: preload this block's weight slices into smem ----
    // wB: 32 columns {q*1024 + bk*8 + j0}, packed float4-over-k, xor swizzle.
    #pragma unroll 4
    for (int p = 0; p < 32; p++) {
        int col = (p >> 3) * H_ + bk * 8 + (p & 7);
        float4 v = ((const float4*)(whnT + (size_t)col * H_))[tid];   // k4 = tid
        wB4[tid * 32 + (p ^ (tid & 31))] = v;
    }
    // wA: 8 rows of wmhnT (jA = bk*8 + p)
    #pragma unroll
    for (int p = 0; p < 8; p++) {
        int jA = bk * 8 + p;
        float4 v = ((const float4*)(wmhnT + (size_t)jA * H_))[tid];
        wA4[tid * 8 + (p ^ (tid & 7))] = v;
    }
    if (tid < 128) d_h[bk*128 + tid] = 0.f;
    unsigned tgt = NBLK;
    gbar(tgt); tgt += NBLK;

    const int outA = tid >> 1, halfA = tid & 1;
    const int bA = outA >> 3, j0A = outA & 7;
    const int jA = bk*8 + j0A;
    const int ksB = tid >> 5, ciB = tid & 31;
    int rci[2], rb[2]; size_t rzoff[2];
    #pragma unroll
    for (int o = 0; o < 2; o++) {
        int out = tid + o*256;
        rci[o] = out >> 4; rb[o] = out & 15;
        int q = rci[o] >> 3, j0 = rci[o] & 7;
        rzoff[o] = (size_t)rb[o]*T_*FH + (size_t)q*H_ + bk*8 + j0;
    }
    const int bG = tid >> 3, j0G = tid & 7;
    float creg = 0.f;

    for (int t = 0; t < T_; t++) {
        float zpre0 = __ldg(&zx[rzoff[0] + (size_t)t*FH]);
        float zpre1 = __ldg(&zx[rzoff[1] + (size_t)t*FH]);
        float mxv = 0.f;
        if (halfA == 0) mxv = __ldg(&mxp[(size_t)(bA*T_ + t)*H_ + jA]);

        {   // stage h [b][k]
            float4* dst = (float4*)stg;
            const float4* src = (const float4*)d_h;
            #pragma unroll
            for (int i = tid; i < 4096; i += 256) dst[i] = __ldcg(src + i);
        }
        __syncthreads();

        {   // phase A: m[b,j] = (h @ wmh_n)[b,j] * mx[b,t,j]; weights from smem
            const float4* hp = (const float4*)(stg + bA*H_) + halfA*128;
            float ax=0.f, ay=0.f, az=0.f, aw=0.f;
            #pragma unroll 8
            for (int i = 0; i < 128; i++) {
                int k4g = halfA*128 + i;
                float4 hv = hp[i];
                float4 wv = wA4[k4g*8 + (j0A ^ (k4g & 7))];
                ax += hv.x*wv.x; ay += hv.y*wv.y;
                az += hv.z*wv.z; aw += hv.w*wv.w;
            }
            red[tid] = (ax + ay) + (az + aw);
        }
        __syncthreads();
        if (halfA == 0) {
            float s = red[tid] + red[tid + 1];
            __stcg(&d_mt[jA*B_ + bA], s * mxv);
        }
        gbar(tgt); tgt += NBLK;

        {   // stage m_t [k][b]
            float4* dst = (float4*)stg;
            const float4* src = (const float4*)d_mt;
            #pragma unroll
            for (int i = tid; i < 4096; i += 256) dst[i] = __ldcg(src + i);
        }
        __syncthreads();

        // phase B: z = zx_t + m @ wh_n; weights from smem
        float acc[16];
        #pragma unroll
        for (int b = 0; b < 16; b++) acc[b] = 0.f;
        {
            #pragma unroll 4
            for (int k4 = 0; k4 < 32; k4++) {
                int k4g = ksB*32 + k4;
                float4 wv = wB4[k4g*32 + (ciB ^ (k4g & 31))];
                #pragma unroll
                for (int u = 0; u < 4; u++) {
                    float wk = (u==0) ? wv.x : (u==1) ? wv.y : (u==2) ? wv.z : wv.w;
                    const float4* m4 = (const float4*)stg + (k4g*4 + u)*4;
                    float4 m0 = m4[0], m1 = m4[1], m2 = m4[2], m3 = m4[3];
                    acc[0]  += m0.x*wk; acc[1]  += m0.y*wk; acc[2]  += m0.z*wk; acc[3]  += m0.w*wk;
                    acc[4]  += m1.x*wk; acc[5]  += m1.y*wk; acc[6]  += m1.z*wk; acc[7]  += m1.w*wk;
                    acc[8]  += m2.x*wk; acc[9]  += m2.y*wk; acc[10] += m2.z*wk; acc[11] += m2.w*wk;
                    acc[12] += m3.x*wk; acc[13] += m3.y*wk; acc[14] += m3.z*wk; acc[15] += m3.w*wk;
                }
            }
        }
        __syncthreads();   // stage reads done; alias as part[]
        #pragma unroll
        for (int b = 0; b < 16; b++)
            stg[(ciB*16 + b)*9 + ksB] = acc[b];
        __syncthreads();

        {   // reduce + add zx
            const float* p0 = stg + (rci[0]*16 + rb[0])*9;
            float s0 = ((p0[0]+p0[1]) + (p0[2]+p0[3])) + ((p0[4]+p0[5]) + (p0[6]+p0[7]));
            stg[8192 + rb[0]*32 + rci[0]] = zpre0 + s0;
            const float* p1 = stg + (rci[1]*16 + rb[1])*9;
            float s1 = ((p1[0]+p1[1]) + (p1[2]+p1[3])) + ((p1[4]+p1[5]) + (p1[6]+p1[7]));
            stg[8192 + rb[1]*32 + rci[1]] = zpre1 + s1;
        }
        __syncthreads();

        if (tid < 128) {
            float zi = stg[8192 + bG*32 +      j0G];
            float zf = stg[8192 + bG*32 +  8 + j0G];
            float zo = stg[8192 + bG*32 + 16 + j0G];
            float zu = stg[8192 + bG*32 + 24 + j0G];
            float ig = 1.f / (1.f + expf(-zi));
            float fg = 1.f / (1.f + expf(-zf));
            float og = 1.f / (1.f + expf(-zo));
            float ug = tanhf(zu);
            creg = fg * creg + ig * ug;
            float h = og * tanhf(creg);
            int col = bk*8 + j0G;
            __stcg(&d_h[bG*H_ + col], h);
            size_t hidx = (size_t)(bG*T_ + t)*H_ + col;
            __nv_bfloat16 hh = __float2bfloat16(h);
            hshi[hidx] = hh;
            hslo[hidx] = __float2bfloat16(h - __bfloat162float(hh));
        }
        gbar(tgt); tgt += NBLK;
    }
}

// ---------------- single-pass online log-softmax NLL ----------------
__global__ void nll_kernel(const float* __restrict__ logits, const int* __restrict__ ys,
                           float* __restrict__ rownll) {
    __shared__ float smx[256], ssm[256];
    int row = blockIdx.x, tid = threadIdx.x;
    const float* l = logits + (size_t)row * V_;
    float m = -3.4e38f, s = 0.f;
    for (int v = tid; v < V_; v += 256) {
        float x = l[v];
        float nm = fmaxf(m, x);
        s = s * expf(m - nm) + expf(x - nm);
        m = nm;
    }
    smx[tid] = m; ssm[tid] = s; __syncthreads();
    for (int k = 128; k > 0; k >>= 1) {
        if (tid < k) {
            float m2 = smx[tid + k], s2 = ssm[tid + k];
            float M = fmaxf(smx[tid], m2);
            ssm[tid] = ssm[tid] * expf(smx[tid] - M) + s2 * expf(m2 - M);
            smx[tid] = M;
        }
        __syncthreads();
    }
    if (tid == 0)
        rownll[row] = -(l[ys[row]] - smx[0] - logf(ssm[0]));
}

__global__ void mean_kernel(const float* __restrict__ rownll, float* __restrict__ out) {
    __shared__ float sred[256];
    int tid = threadIdx.x;
    float s = 0.f;
    for (int i = tid; i < B_*T_; i += 256) s += rownll[i];
    sred[tid] = s; __syncthreads();
    for (int k = 128; k > 0; k >>= 1) {
        if (tid < k) sred[tid] += sred[tid + k];
        __syncthreads();
    }
    if (tid == 0) out[0] = sred[0] / (float)(B_*T_);
}

// ---------------- launcher ----------------
extern "C" void kernel_launch(void* const* d_in, const int* in_sizes, int n_in,
                              void* d_out, int out_size) {
    (void)in_sizes; (void)n_in; (void)out_size;
    const int*   xs      = (const int*)  d_in[0];
    const int*   ys      = (const int*)  d_in[1];
    const float* embed_w = (const float*)d_in[2];
    const float* wx      = (const float*)d_in[3];
    const float* wh      = (const float*)d_in[4];
    const float* wmx     = (const float*)d_in[5];
    const float* wmh     = (const float*)d_in[6];
    const float* bb      = (const float*)d_in[7];
    const float* gx      = (const float*)d_in[8];
    const float* gh      = (const float*)d_in[9];
    const float* gmx     = (const float*)d_in[10];
    const float* gmh     = (const float*)d_in[11];
    const float* pred_w  = (const float*)d_in[12];
    const float* pred_b  = (const float*)d_in[13];
    float* out = (float*)d_out;

    float *p_whnT, *p_wmhnT, *p_zx, *p_mx, *p_logits, *p_rownll;
    float *p_nwx, *p_nwh, *p_nwmx, *p_nwmh;
    __nv_bfloat16 *p_xhi, *p_xlo, *p_wxnThi, *p_wxnTlo, *p_wmxnThi, *p_wmxnTlo;
    __nv_bfloat16 *p_pwhi, *p_pwlo, *p_hshi, *p_hslo;
    cudaGetSymbolAddress((void**)&p_whnT,    d_whnT);
    cudaGetSymbolAddress((void**)&p_wmhnT,   d_wmhnT);
    cudaGetSymbolAddress((void**)&p_zx,      d_zx);
    cudaGetSymbolAddress((void**)&p_mx,      d_mx);
    cudaGetSymbolAddress((void**)&p_logits,  d_logits);
    cudaGetSymbolAddress((void**)&p_rownll,  d_rownll);
    cudaGetSymbolAddress((void**)&p_nwx,     d_nwx);
    cudaGetSymbolAddress((void**)&p_nwh,     d_nwh);
    cudaGetSymbolAddress((void**)&p_nwmx,    d_nwmx);
    cudaGetSymbolAddress((void**)&p_nwmh,    d_nwmh);
    cudaGetSymbolAddress((void**)&p_xhi,     d_xhi);
    cudaGetSymbolAddress((void**)&p_xlo,     d_xlo);
    cudaGetSymbolAddress((void**)&p_wxnThi,  d_wxnThi);
    cudaGetSymbolAddress((void**)&p_wxnTlo,  d_wxnTlo);
    cudaGetSymbolAddress((void**)&p_wmxnThi, d_wmxnThi);
    cudaGetSymbolAddress((void**)&p_wmxnTlo, d_wmxnTlo);
    cudaGetSymbolAddress((void**)&p_pwhi,    d_pwhi);
    cudaGetSymbolAddress((void**)&p_pwlo,    d_pwlo);
    cudaGetSymbolAddress((void**)&p_hshi,    d_hshi);
    cudaGetSymbolAddress((void**)&p_hslo,    d_hslo);

    static bool attr_set = false;
    if (!attr_set) {
        cudaFuncSetAttribute(recur_kernel, cudaFuncAttributeMaxDynamicSharedMemorySize, RS_BYTES);
        cudaFuncSetAttribute(mma_gemm<true>,  cudaFuncAttributeMaxDynamicSharedMemorySize, GSMEM);
        cudaFuncSetAttribute(mma_gemm<false>, cudaFuncAttributeMaxDynamicSharedMemorySize, GSMEM);
        attr_set = true;
    }

    // weight norm
    zero_norms_kernel<<<16, 256>>>();
    sumsq_kernel<<<dim3(FH/256, E_/128), 256>>>(wx,  p_nwx,  E_, FH);
    sumsq_kernel<<<dim3(FH/256, H_/128), 256>>>(wh,  p_nwh,  H_, FH);
    sumsq_kernel<<<dim3(H_/256, E_/128), 256>>>(wmx, p_nwmx, E_, H_);
    sumsq_kernel<<<dim3(H_/256, H_/128), 256>>>(wmh, p_nwmh, H_, H_);
    scaleT_bf16_kernel<<<dim3(FH/32, E_/32), dim3(32,8)>>>(wx,  gx,  p_nwx,  p_wxnThi,  p_wxnTlo,  E_, FH);
    scaleT_bf16_kernel<<<dim3(H_/32, E_/32), dim3(32,8)>>>(wmx, gmx, p_nwmx, p_wmxnThi, p_wmxnTlo, E_, H_);
    scaleT_kernel<<<dim3(FH/32, H_/32), dim3(32,8)>>>(wh,  gh,  p_nwh,  p_whnT,  H_, FH);
    scaleT_kernel<<<dim3(H_/32, H_/32), dim3(32,8)>>>(wmh, gmh, p_nwmh, p_wmhnT, H_, H_);
    split_kernel<<<(int)(((size_t)V_*H_ + 255)/256), 256>>>(pred_w, p_pwhi, p_pwlo, (size_t)V_*H_);

    // embedding (bf16 split)
    embed_kernel<<<B_*T_, 128>>>(xs, embed_w, p_xhi, p_xlo);

    // input projections (tensor cores)
    mma_gemm<true ><<<dim3(FH/128, (B_*T_)/128), 256, GSMEM>>>(
        p_xhi, p_xlo, p_wxnThi, p_wxnTlo, bb, p_zx, B_*T_, FH, E_);
    mma_gemm<false><<<dim3(H_/128, (B_*T_)/128), 256, GSMEM>>>(
        p_xhi, p_xlo, p_wmxnThi, p_wmxnTlo, (const float*)nullptr, p_mx, B_*T_, H_, E_);

    // recurrence
    reset_bar_kernel<<<1, 1>>>();
    recur_kernel<<<NBLK, 256, RS_BYTES>>>(
        p_zx, p_mx, p_wmhnT, p_whnT, p_hshi, p_hslo);

    // logits (tensor cores) + loss
    mma_gemm<true><<<dim3(V_/128, (B_*T_)/128), 256, GSMEM>>>(
        p_hshi, p_hslo, p_pwhi, p_pwlo, pred_b, p_logits, B_*T_, V_, H_);
    nll_kernel<<<B_*T_, 256>>>(p_logits, ys, p_rownll);
    mean_kernel<<<1, 256>>>(p_rownll, out);
}

// round 7
// speedup vs baseline: 9.2534x; 1.2818x over previous
#include <cuda_runtime.h>
#include <cuda_bf16.h>
#include <cstdint>

#define B_  16
#define T_  512
#define V_  8192
#define E_  512
#define H_  1024
#define FH  4096
#define NBLK 128

// ---------------- device scratch ----------------
__device__ __nv_bfloat16 d_xhi[B_*T_*E_], d_xlo[B_*T_*E_];
__device__ __nv_bfloat16 d_wxnThi[(size_t)FH*E_], d_wxnTlo[(size_t)FH*E_];
__device__ __nv_bfloat16 d_wmxnThi[H_*E_], d_wmxnTlo[H_*E_];
__device__ __nv_bfloat16 d_pwhi[(size_t)V_*H_], d_pwlo[(size_t)V_*H_];
__device__ __nv_bfloat16 d_hshi[B_*T_*H_], d_hslo[B_*T_*H_];
__device__ float d_whnT[(size_t)FH*H_];      // [4096][1024]
__device__ float d_wmhnT[H_*H_];             // [1024][1024]
__device__ float d_nwx[FH], d_nwh[FH], d_nwmx[H_], d_nwmh[H_];
__device__ float d_zx[(size_t)B_*T_*FH];
__device__ float d_mx[B_*T_*H_];
__device__ float d_h[B_*H_];
__device__ __nv_bfloat16 d_mthi[B_*H_], d_mtlo[B_*H_];   // m as [b][j] bf16 split
__device__ float d_logits[(size_t)B_*T_*V_];
__device__ float d_rownll[B_*T_];
__device__ unsigned g_barcnt;

// ---------------- helpers ----------------
__device__ __forceinline__ uint32_t smem_u32(const void* p) {
    uint32_t a;
    asm("{ .reg .u64 t; cvta.to.shared.u64 t, %1; cvt.u32.u64 %0, t; }" : "=r"(a) : "l"(p));
    return a;
}
__device__ __forceinline__ void ldm_x4(uint32_t* r, uint32_t addr) {
    asm volatile("ldmatrix.sync.aligned.m8n8.x4.shared.b16 {%0,%1,%2,%3}, [%4];"
                 : "=r"(r[0]), "=r"(r[1]), "=r"(r[2]), "=r"(r[3]) : "r"(addr));
}
__device__ __forceinline__ void ldm_x2(uint32_t* r, uint32_t addr) {
    asm volatile("ldmatrix.sync.aligned.m8n8.x2.shared.b16 {%0,%1}, [%2];"
                 : "=r"(r[0]), "=r"(r[1]) : "r"(addr));
}
__device__ __forceinline__ void mma_bf16(float* c, const uint32_t* a, const uint32_t* b) {
    asm volatile("mma.sync.aligned.m16n8k16.row.col.f32.bf16.bf16.f32 "
                 "{%0,%1,%2,%3}, {%4,%5,%6,%7}, {%8,%9}, {%0,%1,%2,%3};"
                 : "+f"(c[0]), "+f"(c[1]), "+f"(c[2]), "+f"(c[3])
                 : "r"(a[0]), "r"(a[1]), "r"(a[2]), "r"(a[3]), "r"(b[0]), "r"(b[1]));
}
__device__ __forceinline__ uint32_t pk(__nv_bfloat16 a, __nv_bfloat16 b) {
    __nv_bfloat162 t = __halves2bfloat162(a, b);
    return *(uint32_t*)&t;
}

// ---------------- weight norm ----------------
__global__ void zero_norms_kernel() {
    int i = blockIdx.x * 256 + threadIdx.x;
    if (i < FH) { d_nwx[i] = 0.f; d_nwh[i] = 0.f; }
    if (i < H_) { d_nwmx[i] = 0.f; d_nwmh[i] = 0.f; }
}
__global__ void sumsq_kernel(const float* __restrict__ w, float* __restrict__ nrm,
                             int K, int N) {
    int j = blockIdx.x * 256 + threadIdx.x;
    int k0 = blockIdx.y * 128;
    float ss = 0.f;
    #pragma unroll 4
    for (int k = k0; k < k0 + 128; k++) { float v = w[(size_t)k*N + j]; ss += v*v; }
    atomicAdd(&nrm[j], ss);
}
__global__ void scaleT_kernel(const float* __restrict__ w, const float* __restrict__ g,
                              const float* __restrict__ nrm, float* __restrict__ out,
                              int K, int N) {
    __shared__ float tile[32][33];
    int n0 = blockIdx.x * 32, k0 = blockIdx.y * 32;
    int tx = threadIdx.x, ty = threadIdx.y;
    for (int r = ty; r < 32; r += 8)
        tile[r][tx] = w[(size_t)(k0 + r)*N + n0 + tx];
    __syncthreads();
    for (int r = ty; r < 32; r += 8) {
        int n = n0 + r;
        float s = g[n] / fmaxf(sqrtf(nrm[n]), 1e-12f);
        out[(size_t)n*K + k0 + tx] = tile[tx][r] * s;
    }
}
__global__ void scaleT_bf16_kernel(const float* __restrict__ w, const float* __restrict__ g,
                                   const float* __restrict__ nrm,
                                   __nv_bfloat16* __restrict__ ohi,
                                   __nv_bfloat16* __restrict__ olo,
                                   int K, int N) {
    __shared__ float tile[32][33];
    int n0 = blockIdx.x * 32, k0 = blockIdx.y * 32;
    int tx = threadIdx.x, ty = threadIdx.y;
    for (int r = ty; r < 32; r += 8)
        tile[r][tx] = w[(size_t)(k0 + r)*N + n0 + tx];
    __syncthreads();
    for (int r = ty; r < 32; r += 8) {
        int n = n0 + r;
        float s = g[n] / fmaxf(sqrtf(nrm[n]), 1e-12f);
        float v = tile[tx][r] * s;
        __nv_bfloat16 hi = __float2bfloat16(v);
        ohi[(size_t)n*K + k0 + tx] = hi;
        olo[(size_t)n*K + k0 + tx] = __float2bfloat16(v - __bfloat162float(hi));
    }
}
__global__ void split_kernel(const float* __restrict__ w,
                             __nv_bfloat16* __restrict__ ohi,
                             __nv_bfloat16* __restrict__ olo, size_t total) {
    size_t i = (size_t)blockIdx.x * 256 + threadIdx.x;
    if (i >= total) return;
    float v = w[i];
    __nv_bfloat16 hi = __float2bfloat16(v);
    ohi[i] = hi;
    olo[i] = __float2bfloat16(v - __bfloat162float(hi));
}

// ---------------- embedding ----------------
__global__ void embed_kernel(const int* __restrict__ xs, const float* __restrict__ ew,
                             __nv_bfloat16* __restrict__ xhi, __nv_bfloat16* __restrict__ xlo) {
    int r = blockIdx.x;
    int idx = xs[r];
    const float4* src = (const float4*)(ew + (size_t)idx * E_);
    float4 v = src[threadIdx.x];
    if (idx == 0) v = make_float4(0.f, 0.f, 0.f, 0.f);
    size_t base = (size_t)r * E_ + threadIdx.x * 4;
    float vv[4] = {v.x, v.y, v.z, v.w};
    #pragma unroll
    for (int u = 0; u < 4; u++) {
        __nv_bfloat16 hi = __float2bfloat16(vv[u]);
        xhi[base + u] = hi;
        xlo[base + u] = __float2bfloat16(vv[u] - __bfloat162float(hi));
    }
}

// ---------------- mma.sync split-bf16 GEMM (unchanged) ----------------
#define GSMEM 65536

template<bool BIAS>
__global__ void __launch_bounds__(256) mma_gemm(
    const __nv_bfloat16* __restrict__ Ahi, const __nv_bfloat16* __restrict__ Alo,
    const __nv_bfloat16* __restrict__ Bhi, const __nv_bfloat16* __restrict__ Blo,
    const float* __restrict__ bias, float* __restrict__ C,
    int M, int N, int K)
{
    extern __shared__ char smem[];
    const uint32_t sbase = smem_u32(smem);
    const int tid = threadIdx.x, lid = tid & 31, wid = tid >> 5;
    const int wm = (wid & 1) * 64, wn = (wid >> 1) * 32;
    const int bn = blockIdx.x * 128, bm = blockIdx.y * 128;

    float acc[4][4][4];
    #pragma unroll
    for (int mt = 0; mt < 4; mt++)
        #pragma unroll
        for (int nt = 0; nt < 4; nt++)
            #pragma unroll
            for (int u = 0; u < 4; u++) acc[mt][nt][u] = 0.f;

    for (int k0 = 0; k0 < K; k0 += 64) {
        #pragma unroll
        for (int p = 0; p < 16; p++) {
            int i = tid + p * 256;
            int tile = i >> 10, j = i & 1023;
            int row = j >> 3, c = j & 7;
            const __nv_bfloat16* src = (tile == 0) ? Ahi : (tile == 1) ? Alo
                                     : (tile == 2) ? Bhi : Blo;
            int grow = ((tile < 2) ? bm : bn) + row;
            uint4 v = *(const uint4*)(src + (size_t)grow * K + k0 + c * 8);
            *(uint4*)(smem + tile * 16384 + (row * 8 + (c ^ (row & 7))) * 16) = v;
        }
        __syncthreads();
        #pragma unroll
        for (int ks = 0; ks < 4; ks++) {
            uint32_t bh[4][2], bl[4][2];
            {
                int row = wn + (lid & 7);
                int cc = 2 * ks + ((lid >> 3) & 1);
                #pragma unroll
                for (int nt = 0; nt < 4; nt++) {
                    int r = row + nt * 8;
                    uint32_t addr = sbase + 32768 + (r * 8 + (cc ^ (r & 7))) * 16;
                    ldm_x2(bh[nt], addr);
                    ldm_x2(bl[nt], addr + 16384);
                }
            }
            #pragma unroll
            for (int mt = 0; mt < 4; mt++) {
                int r = wm + mt * 16 + (lid & 7) + ((lid >> 3) & 1) * 8;
                int cc = 2 * ks + (lid >> 4);
                uint32_t addr = sbase + (r * 8 + (cc ^ (r & 7))) * 16;
                uint32_t ah[4], al[4];
                ldm_x4(ah, addr);
                ldm_x4(al, addr + 16384);
                #pragma unroll
                for (int nt = 0; nt < 4; nt++) {
                    mma_bf16(acc[mt][nt], ah, bh[nt]);
                    mma_bf16(acc[mt][nt], ah, bl[nt]);
                    mma_bf16(acc[mt][nt], al, bh[nt]);
                }
            }
        }
        __syncthreads();
    }

    const int mrow = (lid >> 2), ncol = (lid & 3) * 2;
    #pragma unroll
    for (int mt = 0; mt < 4; mt++) {
        #pragma unroll
        for (int nt = 0; nt < 4; nt++) {
            int row0 = bm + wm + mt * 16 + mrow;
            int col = bn + wn + nt * 8 + ncol;
            float2 v0 = make_float2(acc[mt][nt][0], acc[mt][nt][1]);
            float2 v1 = make_float2(acc[mt][nt][2], acc[mt][nt][3]);
            if (BIAS) {
                float b0 = bias[col], b1 = bias[col + 1];
                v0.x += b0; v0.y += b1;
                v1.x += b0; v1.y += b1;
            }
            *(float2*)&C[(size_t)row0 * N + col] = v0;
            *(float2*)&C[(size_t)(row0 + 8) * N + col] = v1;
        }
    }
}

// ---------------- persistent recurrence: phase B on mma.sync ----------------
__global__ void reset_bar_kernel() { g_barcnt = 0u; }

__device__ __forceinline__ void gbar(unsigned target) {
    __syncthreads();
    if (threadIdx.x == 0) {
        asm volatile("red.release.gpu.global.add.u32 [%0], %1;"
                     :: "l"(&g_barcnt), "r"(1u) : "memory");
        unsigned v;
        do {
            asm volatile("ld.acquire.gpu.global.u32 %0, [%1];"
                         : "=r"(v) : "l"(&g_barcnt) : "memory");
        } while (v < target);
    }
    __syncthreads();
}

// dyn smem (bytes):
//   [0,      65536)  wBhi : 32 rows x 1024 k bf16, 2048B/row, swizzled
//   [65536, 131072)  wBlo
//   [131072,163840)  wA4  : fp32 float4[2048], [k4 256][j 8] xor-swizzled
//   [163840,229376)  stage: phase A = h fp32 (64KB); phase B = m bf16 hi(32K)+lo(32K)
//                    overlays after sync: part[] floats [0,4608), zz at float ofs 8192
//   [229376,230400)  red[256] fp32
#define S_WBHI  0
#define S_WBLO  65536
#define S_WA    131072
#define S_STG   163840
#define S_RED   229376
#define RS_BYTES 230400

__global__ void __launch_bounds__(256) recur_kernel(
    const float* __restrict__ zx, const float* __restrict__ mxp,
    const float* __restrict__ wmhnT, const float* __restrict__ whnT,
    __nv_bfloat16* __restrict__ hshi, __nv_bfloat16* __restrict__ hslo)
{
    extern __shared__ char smc[];
    float4* wA4 = (float4*)(smc + S_WA);
    float*  stg = (float*)(smc + S_STG);
    float*  red = (float*)(smc + S_RED);
    const uint32_t sbase = smem_u32(smc);
    const int bk = blockIdx.x, tid = threadIdx.x;

    // ---- one-time: preload weights ----
    // wB: 32 z-columns as bf16 hi/lo, row-major [c][k], swizzled for ldmatrix
    #pragma unroll 4
    for (int p = 0; p < 32; p++) {
        int col = (p >> 3) * H_ + bk * 8 + (p & 7);
        float4 v = ((const float4*)(whnT + (size_t)col * H_))[tid];   // k4 = tid
        __nv_bfloat16 hx = __float2bfloat16(v.x), hy = __float2bfloat16(v.y);
        __nv_bfloat16 hz = __float2bfloat16(v.z), hw = __float2bfloat16(v.w);
        __nv_bfloat16 lx = __float2bfloat16(v.x - __bfloat162float(hx));
        __nv_bfloat16 ly = __float2bfloat16(v.y - __bfloat162float(hy));
        __nv_bfloat16 lz = __float2bfloat16(v.z - __bfloat162float(hz));
        __nv_bfloat16 lw = __float2bfloat16(v.w - __bfloat162float(hw));
        uint32_t off = p * 2048 + ((tid * 8) ^ ((p & 7) * 16));
        *(uint2*)(smc + S_WBHI + off) = make_uint2(pk(hx, hy), pk(hz, hw));
        *(uint2*)(smc + S_WBLO + off) = make_uint2(pk(lx, ly), pk(lz, lw));
    }
    // wA: 8 rows of wmhnT (fp32), xor-swizzled float4
    #pragma unroll
    for (int p = 0; p < 8; p++) {
        int jA_ = bk * 8 + p;
        float4 v = ((const float4*)(wmhnT + (size_t)jA_ * H_))[tid];
        wA4[tid * 8 + (p ^ (tid & 7))] = v;
    }
    if (tid < 128) d_h[bk*128 + tid] = 0.f;
    unsigned tgt = NBLK;
    gbar(tgt); tgt += NBLK;

    // phase A mapping
    const int outA = tid >> 1, halfA = tid & 1;
    const int bA = outA >> 3, j0A = outA & 7;
    const int jA = bk*8 + j0A;
    // phase B mma mapping
    const int l = tid & 31, wql = tid >> 5;
    const int arow = (l & 7) + ((l >> 3) & 1) * 8;
    const uint32_t ax = (uint32_t)((arow & 7) * 16);
    const uint32_t asel = ((uint32_t)(l >> 4)) << 4;
    const int brow7 = l & 7;
    const uint32_t bx = (uint32_t)(brow7 * 16);
    const uint32_t bsel = ((uint32_t)((l >> 3) & 1)) << 4;
    // reduce mapping
    int rci[2], rb[2]; size_t rzoff[2];
    #pragma unroll
    for (int o = 0; o < 2; o++) {
        int out = tid + o*256;
        rci[o] = out >> 4; rb[o] = out & 15;
        int q = rci[o] >> 3, j0 = rci[o] & 7;
        rzoff[o] = (size_t)rb[o]*T_*FH + (size_t)q*H_ + bk*8 + j0;
    }
    const int bG = tid >> 3, j0G = tid & 7;
    float creg = 0.f;

    for (int t = 0; t < T_; t++) {
        float zpre0 = __ldg(&zx[rzoff[0] + (size_t)t*FH]);
        float zpre1 = __ldg(&zx[rzoff[1] + (size_t)t*FH]);
        float mxv = 0.f;
        if (halfA == 0) mxv = __ldg(&mxp[(size_t)(bA*T_ + t)*H_ + jA]);

        {   // stage h [b][k] fp32
            float4* dst = (float4*)stg;
            const float4* src = (const float4*)d_h;
            #pragma unroll
            for (int i = tid; i < 4096; i += 256) dst[i] = __ldcg(src + i);
        }
        __syncthreads();

        {   // phase A: m[b,j] = (h @ wmh_n)[b,j] * mx ; FFMA from smem
            const float4* hp = (const float4*)(stg + bA*H_) + halfA*128;
            float a0=0.f, a1=0.f, a2=0.f, a3=0.f;
            #pragma unroll 8
            for (int i = 0; i < 128; i++) {
                int k4g = halfA*128 + i;
                float4 hv = hp[i];
                float4 wv = wA4[k4g*8 + (j0A ^ (k4g & 7))];
                a0 += hv.x*wv.x; a1 += hv.y*wv.y;
                a2 += hv.z*wv.z; a3 += hv.w*wv.w;
            }
            red[tid] = (a0 + a1) + (a2 + a3);
        }
        __syncthreads();
        if (halfA == 0) {
            float s = red[tid] + red[tid + 1];
            float mval = s * mxv;
            __nv_bfloat16 mh = __float2bfloat16(mval);
            __nv_bfloat16 ml = __float2bfloat16(mval - __bfloat162float(mh));
            __stcg((short*)&d_mthi[bA*H_ + jA], *(short*)&mh);
            __stcg((short*)&d_mtlo[bA*H_ + jA], *(short*)&ml);
        }
        gbar(tgt); tgt += NBLK;

        {   // stage m [b][k] bf16 hi(32K)+lo(32K), swizzled rows
            #pragma unroll
            for (int p = 0; p < 16; p++) {
                int i = tid + p * 256;           // 4096 chunks of 16B
                int half = i >> 11;
                int j = i & 2047;
                int b = j >> 7, c = j & 127;
                const uint4* src = (const uint4*)(half ? d_mtlo : d_mthi);
                uint4 v = __ldcg(src + j);
                *(uint4*)(smc + S_STG + half*32768 + b*2048 + ((c*16) ^ ((b&7)*16))) = v;
            }
        }
        __syncthreads();

        // ---- phase B: z = zx_t + m @ wh_n via mma.sync (hi/lo 3 passes) ----
        float acc[4][4];
        #pragma unroll
        for (int nt = 0; nt < 4; nt++)
            #pragma unroll
            for (int u = 0; u < 4; u++) acc[nt][u] = 0.f;
        #pragma unroll
        for (int kc = 0; kc < 8; kc++) {
            uint32_t kb = (uint32_t)(wql*256 + kc*32);
            uint32_t aaddr = sbase + S_STG + (uint32_t)arow*2048 + ((kb + asel) ^ ax);
            uint32_t ah[4], al[4];
            ldm_x4(ah, aaddr);
            ldm_x4(al, aaddr + 32768);
            uint32_t bkb = (kb + bsel) ^ bx;
            #pragma unroll
            for (int nt = 0; nt < 4; nt++) {
                uint32_t baddr = sbase + S_WBHI + (uint32_t)(nt*8 + brow7)*2048 + bkb;
                uint32_t bh[2], bl[2];
                ldm_x2(bh, baddr);
                ldm_x2(bl, baddr + 65536);
                mma_bf16(acc[nt], ah, bh);
                mma_bf16(acc[nt], ah, bl);
                mma_bf16(acc[nt], al, bh);
            }
        }
        __syncthreads();   // all m reads done; overlay stage as part[]
        {
            int bq = l >> 2, cq = (l & 3) * 2;
            #pragma unroll
            for (int nt = 0; nt < 4; nt++) {
                int c0 = nt*8 + cq;
                stg[(c0*16 + bq)*9 + wql]          = acc[nt][0];
                stg[((c0+1)*16 + bq)*9 + wql]      = acc[nt][1];
                stg[(c0*16 + bq + 8)*9 + wql]      = acc[nt][2];
                stg[((c0+1)*16 + bq + 8)*9 + wql]  = acc[nt][3];
            }
        }
        __syncthreads();

        {   // reduce 8 warps + add zx
            const float* p0 = stg + (rci[0]*16 + rb[0])*9;
            float s0 = ((p0[0]+p0[1]) + (p0[2]+p0[3])) + ((p0[4]+p0[5]) + (p0[6]+p0[7]));
            stg[8192 + rb[0]*32 + rci[0]] = zpre0 + s0;
            const float* p1 = stg + (rci[1]*16 + rb[1])*9;
            float s1 = ((p1[0]+p1[1]) + (p1[2]+p1[3])) + ((p1[4]+p1[5]) + (p1[6]+p1[7]));
            stg[8192 + rb[1]*32 + rci[1]] = zpre1 + s1;
        }
        __syncthreads();

        if (tid < 128) {
            float zi = stg[8192 + bG*32 +      j0G];
            float zf = stg[8192 + bG*32 +  8 + j0G];
            float zo = stg[8192 + bG*32 + 16 + j0G];
            float zu = stg[8192 + bG*32 + 24 + j0G];
            float ig = 1.f / (1.f + expf(-zi));
            float fg = 1.f / (1.f + expf(-zf));
            float og = 1.f / (1.f + expf(-zo));
            float ug = tanhf(zu);
            creg = fg * creg + ig * ug;
            float h = og * tanhf(creg);
            int col = bk*8 + j0G;
            __stcg(&d_h[bG*H_ + col], h);
            size_t hidx = (size_t)(bG*T_ + t)*H_ + col;
            __nv_bfloat16 hh = __float2bfloat16(h);
            hshi[hidx] = hh;
            hslo[hidx] = __float2bfloat16(h - __bfloat162float(hh));
        }
        gbar(tgt); tgt += NBLK;
    }
}

// ---------------- single-pass online log-softmax NLL ----------------
__global__ void nll_kernel(const float* __restrict__ logits, const int* __restrict__ ys,
                           float* __restrict__ rownll) {
    __shared__ float smx[256], ssm[256];
    int row = blockIdx.x, tid = threadIdx.x;
    const float* l = logits + (size_t)row * V_;
    float m = -3.4e38f, s = 0.f;
    for (int v = tid; v < V_; v += 256) {
        float x = l[v];
        float nm = fmaxf(m, x);
        s = s * expf(m - nm) + expf(x - nm);
        m = nm;
    }
    smx[tid] = m; ssm[tid] = s; __syncthreads();
    for (int k = 128; k > 0; k >>= 1) {
        if (tid < k) {
            float m2 = smx[tid + k], s2 = ssm[tid + k];
            float M = fmaxf(smx[tid], m2);
            ssm[tid] = ssm[tid] * expf(smx[tid] - M) + s2 * expf(m2 - M);
            smx[tid] = M;
        }
        __syncthreads();
    }
    if (tid == 0)
        rownll[row] = -(l[ys[row]] - smx[0] - logf(ssm[0]));
}

__global__ void mean_kernel(const float* __restrict__ rownll, float* __restrict__ out) {
    __shared__ float sred[256];
    int tid = threadIdx.x;
    float s = 0.f;
    for (int i = tid; i < B_*T_; i += 256) s += rownll[i];
    sred[tid] = s; __syncthreads();
    for (int k = 128; k > 0; k >>= 1) {
        if (tid < k) sred[tid] += sred[tid + k];
        __syncthreads();
    }
    if (tid == 0) out[0] = sred[0] / (float)(B_*T_);
}

// ---------------- launcher ----------------
extern "C" void kernel_launch(void* const* d_in, const int* in_sizes, int n_in,
                              void* d_out, int out_size) {
    (void)in_sizes; (void)n_in; (void)out_size;
    const int*   xs      = (const int*)  d_in[0];
    const int*   ys      = (const int*)  d_in[1];
    const float* embed_w = (const float*)d_in[2];
    const float* wx      = (const float*)d_in[3];
    const float* wh      = (const float*)d_in[4];
    const float* wmx     = (const float*)d_in[5];
    const float* wmh     = (const float*)d_in[6];
    const float* bb      = (const float*)d_in[7];
    const float* gx      = (const float*)d_in[8];
    const float* gh      = (const float*)d_in[9];
    const float* gmx     = (const float*)d_in[10];
    const float* gmh     = (const float*)d_in[11];
    const float* pred_w  = (const float*)d_in[12];
    const float* pred_b  = (const float*)d_in[13];
    float* out = (float*)d_out;

    float *p_whnT, *p_wmhnT, *p_zx, *p_mx, *p_logits, *p_rownll;
    float *p_nwx, *p_nwh, *p_nwmx, *p_nwmh;
    __nv_bfloat16 *p_xhi, *p_xlo, *p_wxnThi, *p_wxnTlo, *p_wmxnThi, *p_wmxnTlo;
    __nv_bfloat16 *p_pwhi, *p_pwlo, *p_hshi, *p_hslo;
    cudaGetSymbolAddress((void**)&p_whnT,    d_whnT);
    cudaGetSymbolAddress((void**)&p_wmhnT,   d_wmhnT);
    cudaGetSymbolAddress((void**)&p_zx,      d_zx);
    cudaGetSymbolAddress((void**)&p_mx,      d_mx);
    cudaGetSymbolAddress((void**)&p_logits,  d_logits);
    cudaGetSymbolAddress((void**)&p_rownll,  d_rownll);
    cudaGetSymbolAddress((void**)&p_nwx,     d_nwx);
    cudaGetSymbolAddress((void**)&p_nwh,     d_nwh);
    cudaGetSymbolAddress((void**)&p_nwmx,    d_nwmx);
    cudaGetSymbolAddress((void**)&p_nwmh,    d_nwmh);
    cudaGetSymbolAddress((void**)&p_xhi,     d_xhi);
    cudaGetSymbolAddress((void**)&p_xlo,     d_xlo);
    cudaGetSymbolAddress((void**)&p_wxnThi,  d_wxnThi);
    cudaGetSymbolAddress((void**)&p_wxnTlo,  d_wxnTlo);
    cudaGetSymbolAddress((void**)&p_wmxnThi, d_wmxnThi);
    cudaGetSymbolAddress((void**)&p_wmxnTlo, d_wmxnTlo);
    cudaGetSymbolAddress((void**)&p_pwhi,    d_pwhi);
    cudaGetSymbolAddress((void**)&p_pwlo,    d_pwlo);
    cudaGetSymbolAddress((void**)&p_hshi,    d_hshi);
    cudaGetSymbolAddress((void**)&p_hslo,    d_hslo);

    static bool attr_set = false;
    if (!attr_set) {
        cudaFuncSetAttribute(recur_kernel, cudaFuncAttributeMaxDynamicSharedMemorySize, RS_BYTES);
        cudaFuncSetAttribute(mma_gemm<true>,  cudaFuncAttributeMaxDynamicSharedMemorySize, GSMEM);
        cudaFuncSetAttribute(mma_gemm<false>, cudaFuncAttributeMaxDynamicSharedMemorySize, GSMEM);
        attr_set = true;
    }

    // weight norm
    zero_norms_kernel<<<16, 256>>>();
    sumsq_kernel<<<dim3(FH/256, E_/128), 256>>>(wx,  p_nwx,  E_, FH);
    sumsq_kernel<<<dim3(FH/256, H_/128), 256>>>(wh,  p_nwh,  H_, FH);
    sumsq_kernel<<<dim3(H_/256, E_/128), 256>>>(wmx, p_nwmx, E_, H_);
    sumsq_kernel<<<dim3(H_/256, H_/128), 256>>>(wmh, p_nwmh, H_, H_);
    scaleT_bf16_kernel<<<dim3(FH/32, E_/32), dim3(32,8)>>>(wx,  gx,  p_nwx,  p_wxnThi,  p_wxnTlo,  E_, FH);
    scaleT_bf16_kernel<<<dim3(H_/32, E_/32), dim3(32,8)>>>(wmx, gmx, p_nwmx, p_wmxnThi, p_wmxnTlo, E_, H_);
    scaleT_kernel<<<dim3(FH/32, H_/32), dim3(32,8)>>>(wh,  gh,  p_nwh,  p_whnT,  H_, FH);
    scaleT_kernel<<<dim3(H_/32, H_/32), dim3(32,8)>>>(wmh, gmh, p_nwmh, p_wmhnT, H_, H_);
    split_kernel<<<(int)(((size_t)V_*H_ + 255)/256), 256>>>(pred_w, p_pwhi, p_pwlo, (size_t)V_*H_);

    // embedding (bf16 split)
    embed_kernel<<<B_*T_, 128>>>(xs, embed_w, p_xhi, p_xlo);

    // input projections (tensor cores)
    mma_gemm<true ><<<dim3(FH/128, (B_*T_)/128), 256, GSMEM>>>(
        p_xhi, p_xlo, p_wxnThi, p_wxnTlo, bb, p_zx, B_*T_, FH, E_);
    mma_gemm<false><<<dim3(H_/128, (B_*T_)/128), 256, GSMEM>>>(
        p_xhi, p_xlo, p_wmxnThi, p_wmxnTlo, (const float*)nullptr, p_mx, B_*T_, H_, E_);

    // recurrence
    reset_bar_kernel<<<1, 1>>>();
    recur_kernel<<<NBLK, 256, RS_BYTES>>>(
        p_zx, p_mx, p_wmhnT, p_whnT, p_hshi, p_hslo);

    // logits (tensor cores) + loss
    mma_gemm<true><<<dim3(V_/128, (B_*T_)/128), 256, GSMEM>>>(
        p_hshi, p_hslo, p_pwhi, p_pwlo, pred_b, p_logits, B_*T_, V_, H_);
    nll_kernel<<<B_*T_, 256>>>(p_logits, ys, p_rownll);
    mean_kernel<<<1, 256>>>(p_rownll, out);
}

// round 8
// speedup vs baseline: 14.6236x; 1.5804x over previous
#include <cuda_runtime.h>
#include <cuda_bf16.h>
#include <cstdint>

#define B_  16
#define T_  512
#define V_  8192
#define E_  512
#define H_  1024
#define FH  4096
#define NBLK 128

// ---------------- device scratch ----------------
__device__ __nv_bfloat16 d_xhi[B_*T_*E_], d_xlo[B_*T_*E_];
__device__ __nv_bfloat16 d_wxnThi[(size_t)FH*E_], d_wxnTlo[(size_t)FH*E_];
__device__ __nv_bfloat16 d_wmxnThi[H_*E_], d_wmxnTlo[H_*E_];
__device__ __nv_bfloat16 d_pwhi[(size_t)V_*H_], d_pwlo[(size_t)V_*H_];
__device__ __nv_bfloat16 d_hshi[B_*T_*H_], d_hslo[B_*T_*H_];
__device__ float d_whnT[(size_t)FH*H_];      // [4096][1024]
__device__ float d_wmhnT[H_*H_];             // [1024][1024]
__device__ float d_nwx[FH], d_nwh[FH], d_nwmx[H_], d_nwmh[H_];
__device__ float d_zx[(size_t)B_*T_*FH];
__device__ float d_mx[B_*T_*H_];
__device__ __nv_bfloat16 d_hhi[B_*H_], d_hlo[B_*H_];     // h state bf16 split
__device__ __nv_bfloat16 d_mthi[B_*H_], d_mtlo[B_*H_];   // m bf16 split
__device__ float d_logits[(size_t)B_*T_*V_];
__device__ float d_rownll[B_*T_];
__device__ unsigned g_barcnt;

// ---------------- helpers ----------------
__device__ __forceinline__ uint32_t smem_u32(const void* p) {
    uint32_t a;
    asm("{ .reg .u64 t; cvta.to.shared.u64 t, %1; cvt.u32.u64 %0, t; }" : "=r"(a) : "l"(p));
    return a;
}
__device__ __forceinline__ void ldm_x4(uint32_t* r, uint32_t addr) {
    asm volatile("ldmatrix.sync.aligned.m8n8.x4.shared.b16 {%0,%1,%2,%3}, [%4];"
                 : "=r"(r[0]), "=r"(r[1]), "=r"(r[2]), "=r"(r[3]) : "r"(addr));
}
__device__ __forceinline__ void ldm_x2(uint32_t* r, uint32_t addr) {
    asm volatile("ldmatrix.sync.aligned.m8n8.x2.shared.b16 {%0,%1}, [%2];"
                 : "=r"(r[0]), "=r"(r[1]) : "r"(addr));
}
__device__ __forceinline__ void mma_bf16(float* c, const uint32_t* a, const uint32_t* b) {
    asm volatile("mma.sync.aligned.m16n8k16.row.col.f32.bf16.bf16.f32 "
                 "{%0,%1,%2,%3}, {%4,%5,%6,%7}, {%8,%9}, {%0,%1,%2,%3};"
                 : "+f"(c[0]), "+f"(c[1]), "+f"(c[2]), "+f"(c[3])
                 : "r"(a[0]), "r"(a[1]), "r"(a[2]), "r"(a[3]), "r"(b[0]), "r"(b[1]));
}
__device__ __forceinline__ uint32_t pk(__nv_bfloat16 a, __nv_bfloat16 b) {
    __nv_bfloat162 t = __halves2bfloat162(a, b);
    return *(uint32_t*)&t;
}
__device__ __forceinline__ void cpa16(uint32_t saddr, const void* g) {
    asm volatile("cp.async.cg.shared.global [%0], [%1], 16;" :: "r"(saddr), "l"(g) : "memory");
}

// ---------------- weight norm ----------------
__global__ void zero_norms_kernel() {
    int i = blockIdx.x * 256 + threadIdx.x;
    if (i < FH) { d_nwx[i] = 0.f; d_nwh[i] = 0.f; }
    if (i < H_) { d_nwmx[i] = 0.f; d_nwmh[i] = 0.f; }
}
__global__ void sumsq_kernel(const float* __restrict__ w, float* __restrict__ nrm,
                             int K, int N) {
    int j = blockIdx.x * 256 + threadIdx.x;
    int k0 = blockIdx.y * 128;
    float ss = 0.f;
    #pragma unroll 4
    for (int k = k0; k < k0 + 128; k++) { float v = w[(size_t)k*N + j]; ss += v*v; }
    atomicAdd(&nrm[j], ss);
}
__global__ void scaleT_kernel(const float* __restrict__ w, const float* __restrict__ g,
                              const float* __restrict__ nrm, float* __restrict__ out,
                              int K, int N) {
    __shared__ float tile[32][33];
    int n0 = blockIdx.x * 32, k0 = blockIdx.y * 32;
    int tx = threadIdx.x, ty = threadIdx.y;
    for (int r = ty; r < 32; r += 8)
        tile[r][tx] = w[(size_t)(k0 + r)*N + n0 + tx];
    __syncthreads();
    for (int r = ty; r < 32; r += 8) {
        int n = n0 + r;
        float s = g[n] / fmaxf(sqrtf(nrm[n]), 1e-12f);
        out[(size_t)n*K + k0 + tx] = tile[tx][r] * s;
    }
}
__global__ void scaleT_bf16_kernel(const float* __restrict__ w, const float* __restrict__ g,
                                   const float* __restrict__ nrm,
                                   __nv_bfloat16* __restrict__ ohi,
                                   __nv_bfloat16* __restrict__ olo,
                                   int K, int N) {
    __shared__ float tile[32][33];
    int n0 = blockIdx.x * 32, k0 = blockIdx.y * 32;
    int tx = threadIdx.x, ty = threadIdx.y;
    for (int r = ty; r < 32; r += 8)
        tile[r][tx] = w[(size_t)(k0 + r)*N + n0 + tx];
    __syncthreads();
    for (int r = ty; r < 32; r += 8) {
        int n = n0 + r;
        float s = g[n] / fmaxf(sqrtf(nrm[n]), 1e-12f);
        float v = tile[tx][r] * s;
        __nv_bfloat16 hi = __float2bfloat16(v);
        ohi[(size_t)n*K + k0 + tx] = hi;
        olo[(size_t)n*K + k0 + tx] = __float2bfloat16(v - __bfloat162float(hi));
    }
}
__global__ void split_kernel(const float* __restrict__ w,
                             __nv_bfloat16* __restrict__ ohi,
                             __nv_bfloat16* __restrict__ olo, size_t total) {
    size_t i = (size_t)blockIdx.x * 256 + threadIdx.x;
    if (i >= total) return;
    float v = w[i];
    __nv_bfloat16 hi = __float2bfloat16(v);
    ohi[i] = hi;
    olo[i] = __float2bfloat16(v - __bfloat162float(hi));
}

// ---------------- embedding ----------------
__global__ void embed_kernel(const int* __restrict__ xs, const float* __restrict__ ew,
                             __nv_bfloat16* __restrict__ xhi, __nv_bfloat16* __restrict__ xlo) {
    int r = blockIdx.x;
    int idx = xs[r];
    const float4* src = (const float4*)(ew + (size_t)idx * E_);
    float4 v = src[threadIdx.x];
    if (idx == 0) v = make_float4(0.f, 0.f, 0.f, 0.f);
    size_t base = (size_t)r * E_ + threadIdx.x * 4;
    float vv[4] = {v.x, v.y, v.z, v.w};
    #pragma unroll
    for (int u = 0; u < 4; u++) {
        __nv_bfloat16 hi = __float2bfloat16(vv[u]);
        xhi[base + u] = hi;
        xlo[base + u] = __float2bfloat16(vv[u] - __bfloat162float(hi));
    }
}

// ---------------- mma.sync split-bf16 GEMM, cp.async double-buffered ----------------
#define GSMEM 131072

template<bool BIAS>
__global__ void __launch_bounds__(256) mma_gemm(
    const __nv_bfloat16* __restrict__ Ahi, const __nv_bfloat16* __restrict__ Alo,
    const __nv_bfloat16* __restrict__ Bhi, const __nv_bfloat16* __restrict__ Blo,
    const float* __restrict__ bias, float* __restrict__ C,
    int M, int N, int K)
{
    extern __shared__ char smem[];
    const uint32_t sbase = smem_u32(smem);
    const int tid = threadIdx.x, lid = tid & 31, wid = tid >> 5;
    const int wm = (wid & 1) * 64, wn = (wid >> 1) * 32;
    const int bn = blockIdx.x * 128, bm = blockIdx.y * 128;

    float acc[4][4][4];
    #pragma unroll
    for (int mt = 0; mt < 4; mt++)
        #pragma unroll
        for (int nt = 0; nt < 4; nt++)
            #pragma unroll
            for (int u = 0; u < 4; u++) acc[mt][nt][u] = 0.f;

    auto issue = [&](int ch, int buf) {
        int k0 = ch << 6;
        #pragma unroll
        for (int p = 0; p < 16; p++) {
            int i = tid + p * 256;
            int tile = i >> 10, j = i & 1023;
            int row = j >> 3, c = j & 7;
            const __nv_bfloat16* src = (tile == 0) ? Ahi : (tile == 1) ? Alo
                                     : (tile == 2) ? Bhi : Blo;
            int grow = ((tile < 2) ? bm : bn) + row;
            uint32_t sa = sbase + (uint32_t)buf*65536 + tile*16384
                        + (row * 8 + (c ^ (row & 7))) * 16;
            cpa16(sa, src + (size_t)grow * K + k0 + c * 8);
        }
        asm volatile("cp.async.commit_group;" ::: "memory");
    };

    const int nchunk = K >> 6;
    issue(0, 0);
    for (int ch = 0; ch < nchunk; ch++) {
        if (ch + 1 < nchunk) {
            issue(ch + 1, (ch + 1) & 1);
            asm volatile("cp.async.wait_group 1;" ::: "memory");
        } else {
            asm volatile("cp.async.wait_group 0;" ::: "memory");
        }
        __syncthreads();
        const uint32_t boff = sbase + (uint32_t)((ch & 1) * 65536);
        #pragma unroll
        for (int ks = 0; ks < 4; ks++) {
            uint32_t bh[4][2], bl[4][2];
            {
                int row = wn + (lid & 7);
                int cc = 2 * ks + ((lid >> 3) & 1);
                #pragma unroll
                for (int nt = 0; nt < 4; nt++) {
                    int r = row + nt * 8;
                    uint32_t addr = boff + 32768 + (r * 8 + (cc ^ (r & 7))) * 16;
                    ldm_x2(bh[nt], addr);
                    ldm_x2(bl[nt], addr + 16384);
                }
            }
            #pragma unroll
            for (int mt = 0; mt < 4; mt++) {
                int r = wm + mt * 16 + (lid & 7) + ((lid >> 3) & 1) * 8;
                int cc = 2 * ks + (lid >> 4);
                uint32_t addr = boff + (r * 8 + (cc ^ (r & 7))) * 16;
                uint32_t ah[4], al[4];
                ldm_x4(ah, addr);
                ldm_x4(al, addr + 16384);
                #pragma unroll
                for (int nt = 0; nt < 4; nt++) {
                    mma_bf16(acc[mt][nt], ah, bh[nt]);
                    mma_bf16(acc[mt][nt], ah, bl[nt]);
                    mma_bf16(acc[mt][nt], al, bh[nt]);
                }
            }
        }
        __syncthreads();
    }

    const int mrow = (lid >> 2), ncol = (lid & 3) * 2;
    #pragma unroll
    for (int mt = 0; mt < 4; mt++) {
        #pragma unroll
        for (int nt = 0; nt < 4; nt++) {
            int row0 = bm + wm + mt * 16 + mrow;
            int col = bn + wn + nt * 8 + ncol;
            float2 v0 = make_float2(acc[mt][nt][0], acc[mt][nt][1]);
            float2 v1 = make_float2(acc[mt][nt][2], acc[mt][nt][3]);
            if (BIAS) {
                float b0 = bias[col], b1 = bias[col + 1];
                v0.x += b0; v0.y += b1;
                v1.x += b0; v1.y += b1;
            }
            *(float2*)&C[(size_t)row0 * N + col] = v0;
            *(float2*)&C[(size_t)(row0 + 8) * N + col] = v1;
        }
    }
}

// ---------------- persistent recurrence: both phases on mma.sync ----------------
__global__ void reset_bar_kernel() { g_barcnt = 0u; }

__device__ __forceinline__ void gbar(unsigned target) {
    __syncthreads();
    if (threadIdx.x == 0) {
        asm volatile("red.release.gpu.global.add.u32 [%0], %1;"
                     :: "l"(&g_barcnt), "r"(1u) : "memory");
        unsigned v;
        do {
            asm volatile("ld.acquire.gpu.global.u32 %0, [%1];"
                         : "=r"(v) : "l"(&g_barcnt) : "memory");
        } while (v < target);
    }
    __syncthreads();
}

// dyn smem (bytes):
//   [0,      65536)  wBhi : 32 rows x 1024 k bf16, 2048B/row, swizzled
//   [65536, 131072)  wBlo
//   [131072,147456)  wAhi : 8 rows x 1024 k bf16
//   [147456,163840)  wAlo
//   [163840,229376)  stage: h or m bf16 hi(32K)+lo(32K); overlays: part[], zz @ float ofs 8192
#define S_WBHI  0
#define S_WBLO  65536
#define S_WAHI  131072
#define S_WALO  147456
#define S_STG   163840
#define RS_BYTES 229376

__global__ void __launch_bounds__(256) recur_kernel(
    const float* __restrict__ zx, const float* __restrict__ mxp,
    const float* __restrict__ wmhnT, const float* __restrict__ whnT,
    __nv_bfloat16* __restrict__ hshi, __nv_bfloat16* __restrict__ hslo)
{
    extern __shared__ char smc[];
    float* stg = (float*)(smc + S_STG);
    const uint32_t sbase = smem_u32(smc);
    const int bk = blockIdx.x, tid = threadIdx.x;

    // ---- one-time weight preload (bf16 hi/lo, ldmatrix-swizzled rows) ----
    #pragma unroll 4
    for (int p = 0; p < 32; p++) {
        int col = (p >> 3) * H_ + bk * 8 + (p & 7);
        float4 v = ((const float4*)(whnT + (size_t)col * H_))[tid];
        __nv_bfloat16 hx = __float2bfloat16(v.x), hy = __float2bfloat16(v.y);
        __nv_bfloat16 hz = __float2bfloat16(v.z), hw = __float2bfloat16(v.w);
        __nv_bfloat16 lx = __float2bfloat16(v.x - __bfloat162float(hx));
        __nv_bfloat16 ly = __float2bfloat16(v.y - __bfloat162float(hy));
        __nv_bfloat16 lz = __float2bfloat16(v.z - __bfloat162float(hz));
        __nv_bfloat16 lw = __float2bfloat16(v.w - __bfloat162float(hw));
        uint32_t off = p * 2048 + ((tid * 8) ^ ((p & 7) * 16));
        *(uint2*)(smc + S_WBHI + off) = make_uint2(pk(hx, hy), pk(hz, hw));
        *(uint2*)(smc + S_WBLO + off) = make_uint2(pk(lx, ly), pk(lz, lw));
    }
    #pragma unroll
    for (int p = 0; p < 8; p++) {
        int col = bk * 8 + p;
        float4 v = ((const float4*)(wmhnT + (size_t)col * H_))[tid];
        __nv_bfloat16 hx = __float2bfloat16(v.x), hy = __float2bfloat16(v.y);
        __nv_bfloat16 hz = __float2bfloat16(v.z), hw = __float2bfloat16(v.w);
        __nv_bfloat16 lx = __float2bfloat16(v.x - __bfloat162float(hx));
        __nv_bfloat16 ly = __float2bfloat16(v.y - __bfloat162float(hy));
        __nv_bfloat16 lz = __float2bfloat16(v.z - __bfloat162float(hz));
        __nv_bfloat16 lw = __float2bfloat16(v.w - __bfloat162float(hw));
        uint32_t off = p * 2048 + ((tid * 8) ^ (p * 16));
        *(uint2*)(smc + S_WAHI + off) = make_uint2(pk(hx, hy), pk(hz, hw));
        *(uint2*)(smc + S_WALO + off) = make_uint2(pk(lx, ly), pk(lz, lw));
    }
    // zero h state (this block's 8 columns)
    if (tid < 128) {
        int b = tid >> 3, col = bk*8 + (tid & 7);
        ((short*)d_hhi)[b*H_ + col] = 0;
        ((short*)d_hlo)[b*H_ + col] = 0;
    }
    unsigned tgt = NBLK;
    gbar(tgt); tgt += NBLK;

    // mma lane mapping (shared by both phases)
    const int l = tid & 31, wql = tid >> 5;
    const int arow = (l & 7) + ((l >> 3) & 1) * 8;
    const uint32_t ax = (uint32_t)((arow & 7) * 16);
    const uint32_t asel = ((uint32_t)(l >> 4)) << 4;
    const int brow7 = l & 7;
    const uint32_t bx = (uint32_t)(brow7 * 16);
    const uint32_t bsel = ((uint32_t)((l >> 3) & 1)) << 4;
    // reduce-B mapping
    int rci[2], rb[2]; size_t rzoff[2];
    #pragma unroll
    for (int o = 0; o < 2; o++) {
        int out = tid + o*256;
        rci[o] = out >> 4; rb[o] = out & 15;
        int q = rci[o] >> 3, j0 = rci[o] & 7;
        rzoff[o] = (size_t)rb[o]*T_*FH + (size_t)q*H_ + bk*8 + j0;
    }
    const int bG = tid >> 3, j0G = tid & 7;
    float creg = 0.f;

    for (int t = 0; t < T_; t++) {
        float zpre0 = __ldg(&zx[rzoff[0] + (size_t)t*FH]);
        float zpre1 = __ldg(&zx[rzoff[1] + (size_t)t*FH]);
        float mxv = 0.f;
        if (tid < 128) mxv = __ldg(&mxp[(size_t)(bG*T_ + t)*H_ + bk*8 + j0G]);

        {   // stage h [b][k] bf16 hi/lo, swizzled rows
            #pragma unroll
            for (int p = 0; p < 16; p++) {
                int i = tid + p * 256;
                int half = i >> 11, j = i & 2047;
                int b = j >> 7, c = j & 127;
                const uint4* src = (const uint4*)(half ? d_hlo : d_hhi);
                uint4 v = __ldcg(src + j);
                *(uint4*)(smc + S_STG + half*32768 + b*2048 + ((c*16) ^ ((b&7)*16))) = v;
            }
        }
        __syncthreads();

        // ---- phase A: m = (h @ wmh) * mx via mma (hi/lo 3 passes) ----
        float accA[4] = {0.f, 0.f, 0.f, 0.f};
        #pragma unroll
        for (int kc = 0; kc < 8; kc++) {
            uint32_t kb = (uint32_t)(wql*256 + kc*32);
            uint32_t aaddr = sbase + S_STG + (uint32_t)arow*2048 + ((kb + asel) ^ ax);
            uint32_t ah[4], al[4];
            ldm_x4(ah, aaddr);
            ldm_x4(al, aaddr + 32768);
            uint32_t bkb = (kb + bsel) ^ bx;
            uint32_t baddr = sbase + S_WAHI + (uint32_t)brow7*2048 + bkb;
            uint32_t bh2[2], bl2[2];
            ldm_x2(bh2, baddr);
            ldm_x2(bl2, baddr + 16384);
            mma_bf16(accA, ah, bh2);
            mma_bf16(accA, ah, bl2);
            mma_bf16(accA, al, bh2);
        }
        __syncthreads();    // h stage dead; overlay as part[]
        {
            int bq = l >> 2, cq = (l & 3) * 2;
            stg[(cq*16 + bq)*9 + wql]           = accA[0];
            stg[((cq+1)*16 + bq)*9 + wql]       = accA[1];
            stg[(cq*16 + bq + 8)*9 + wql]       = accA[2];
            stg[((cq+1)*16 + bq + 8)*9 + wql]   = accA[3];
        }
        __syncthreads();
        if (tid < 128) {
            const float* pp = stg + (j0G*16 + bG)*9;
            float s = ((pp[0]+pp[1]) + (pp[2]+pp[3])) + ((pp[4]+pp[5]) + (pp[6]+pp[7]));
            float mval = s * mxv;
            __nv_bfloat16 mh = __float2bfloat16(mval);
            __nv_bfloat16 ml = __float2bfloat16(mval - __bfloat162float(mh));
            __stcg((short*)&d_mthi[bG*H_ + bk*8 + j0G], *(short*)&mh);
            __stcg((short*)&d_mtlo[bG*H_ + bk*8 + j0G], *(short*)&ml);
        }
        gbar(tgt); tgt += NBLK;

        {   // stage m [b][k] bf16 hi/lo
            #pragma unroll
            for (int p = 0; p < 16; p++) {
                int i = tid + p * 256;
                int half = i >> 11, j = i & 2047;
                int b = j >> 7, c = j & 127;
                const uint4* src = (const uint4*)(half ? d_mtlo : d_mthi);
                uint4 v = __ldcg(src + j);
                *(uint4*)(smc + S_STG + half*32768 + b*2048 + ((c*16) ^ ((b&7)*16))) = v;
            }
        }
        __syncthreads();

        // ---- phase B: z = zx_t + m @ wh via mma (hi/lo 3 passes) ----
        float acc[4][4];
        #pragma unroll
        for (int nt = 0; nt < 4; nt++)
            #pragma unroll
            for (int u = 0; u < 4; u++) acc[nt][u] = 0.f;
        #pragma unroll
        for (int kc = 0; kc < 8; kc++) {
            uint32_t kb = (uint32_t)(wql*256 + kc*32);
            uint32_t aaddr = sbase + S_STG + (uint32_t)arow*2048 + ((kb + asel) ^ ax);
            uint32_t ah[4], al[4];
            ldm_x4(ah, aaddr);
            ldm_x4(al, aaddr + 32768);
            uint32_t bkb = (kb + bsel) ^ bx;
            #pragma unroll
            for (int nt = 0; nt < 4; nt++) {
                uint32_t baddr = sbase + S_WBHI + (uint32_t)(nt*8 + brow7)*2048 + bkb;
                uint32_t bh[2], bl[2];
                ldm_x2(bh, baddr);
                ldm_x2(bl, baddr + 65536);
                mma_bf16(acc[nt], ah, bh);
                mma_bf16(acc[nt], ah, bl);
                mma_bf16(acc[nt], al, bh);
            }
        }
        __syncthreads();    // m stage dead; overlay as part[]
        {
            int bq = l >> 2, cq = (l & 3) * 2;
            #pragma unroll
            for (int nt = 0; nt < 4; nt++) {
                int c0 = nt*8 + cq;
                stg[(c0*16 + bq)*9 + wql]          = acc[nt][0];
                stg[((c0+1)*16 + bq)*9 + wql]      = acc[nt][1];
                stg[(c0*16 + bq + 8)*9 + wql]      = acc[nt][2];
                stg[((c0+1)*16 + bq + 8)*9 + wql]  = acc[nt][3];
            }
        }
        __syncthreads();

        {   // reduce 8 warps + add zx
            const float* p0 = stg + (rci[0]*16 + rb[0])*9;
            float s0 = ((p0[0]+p0[1]) + (p0[2]+p0[3])) + ((p0[4]+p0[5]) + (p0[6]+p0[7]));
            stg[8192 + rb[0]*32 + rci[0]] = zpre0 + s0;
            const float* p1 = stg + (rci[1]*16 + rb[1])*9;
            float s1 = ((p1[0]+p1[1]) + (p1[2]+p1[3])) + ((p1[4]+p1[5]) + (p1[6]+p1[7]));
            stg[8192 + rb[1]*32 + rci[1]] = zpre1 + s1;
        }
        __syncthreads();

        if (tid < 128) {
            float zi = stg[8192 + bG*32 +      j0G];
            float zf = stg[8192 + bG*32 +  8 + j0G];
            float zo = stg[8192 + bG*32 + 16 + j0G];
            float zu = stg[8192 + bG*32 + 24 + j0G];
            float ig = 1.f / (1.f + expf(-zi));
            float fg = 1.f / (1.f + expf(-zf));
            float og = 1.f / (1.f + expf(-zo));
            float ug = tanhf(zu);
            creg = fg * creg + ig * ug;
            float h = og * tanhf(creg);
            int col = bk*8 + j0G;
            __nv_bfloat16 hh = __float2bfloat16(h);
            __nv_bfloat16 hl = __float2bfloat16(h - __bfloat162float(hh));
            __stcg((short*)&d_hhi[bG*H_ + col], *(short*)&hh);
            __stcg((short*)&d_hlo[bG*H_ + col], *(short*)&hl);
            size_t hidx = (size_t)(bG*T_ + t)*H_ + col;
            hshi[hidx] = hh;
            hslo[hidx] = hl;
        }
        gbar(tgt); tgt += NBLK;
    }
}

// ---------------- single-pass online log-softmax NLL ----------------
__global__ void nll_kernel(const float* __restrict__ logits, const int* __restrict__ ys,
                           float* __restrict__ rownll) {
    __shared__ float smx[256], ssm[256];
    int row = blockIdx.x, tid = threadIdx.x;
    const float* l = logits + (size_t)row * V_;
    float m = -3.4e38f, s = 0.f;
    for (int v = tid; v < V_; v += 256) {
        float x = l[v];
        float nm = fmaxf(m, x);
        s = s * expf(m - nm) + expf(x - nm);
        m = nm;
    }
    smx[tid] = m; ssm[tid] = s; __syncthreads();
    for (int k = 128; k > 0; k >>= 1) {
        if (tid < k) {
            float m2 = smx[tid + k], s2 = ssm[tid + k];
            float M = fmaxf(smx[tid], m2);
            ssm[tid] = ssm[tid] * expf(smx[tid] - M) + s2 * expf(m2 - M);
            smx[tid] = M;
        }
        __syncthreads();
    }
    if (tid == 0)
        rownll[row] = -(l[ys[row]] - smx[0] - logf(ssm[0]));
}

__global__ void mean_kernel(const float* __restrict__ rownll, float* __restrict__ out) {
    __shared__ float sred[256];
    int tid = threadIdx.x;
    float s = 0.f;
    for (int i = tid; i < B_*T_; i += 256) s += rownll[i];
    sred[tid] = s; __syncthreads();
    for (int k = 128; k > 0; k >>= 1) {
        if (tid < k) sred[tid] += sred[tid + k];
        __syncthreads();
    }
    if (tid == 0) out[0] = sred[0] / (float)(B_*T_);
}

// ---------------- launcher ----------------
extern "C" void kernel_launch(void* const* d_in, const int* in_sizes, int n_in,
                              void* d_out, int out_size) {
    (void)in_sizes; (void)n_in; (void)out_size;
    const int*   xs      = (const int*)  d_in[0];
    const int*   ys      = (const int*)  d_in[1];
    const float* embed_w = (const float*)d_in[2];
    const float* wx      = (const float*)d_in[3];
    const float* wh      = (const float*)d_in[4];
    const float* wmx     = (const float*)d_in[5];
    const float* wmh     = (const float*)d_in[6];
    const float* bb      = (const float*)d_in[7];
    const float* gx      = (const float*)d_in[8];
    const float* gh      = (const float*)d_in[9];
    const float* gmx     = (const float*)d_in[10];
    const float* gmh     = (const float*)d_in[11];
    const float* pred_w  = (const float*)d_in[12];
    const float* pred_b  = (const float*)d_in[13];
    float* out = (float*)d_out;

    float *p_whnT, *p_wmhnT, *p_zx, *p_mx, *p_logits, *p_rownll;
    float *p_nwx, *p_nwh, *p_nwmx, *p_nwmh;
    __nv_bfloat16 *p_xhi, *p_xlo, *p_wxnThi, *p_wxnTlo, *p_wmxnThi, *p_wmxnTlo;
    __nv_bfloat16 *p_pwhi, *p_pwlo, *p_hshi, *p_hslo;
    cudaGetSymbolAddress((void**)&p_whnT,    d_whnT);
    cudaGetSymbolAddress((void**)&p_wmhnT,   d_wmhnT);
    cudaGetSymbolAddress((void**)&p_zx,      d_zx);
    cudaGetSymbolAddress((void**)&p_mx,      d_mx);
    cudaGetSymbolAddress((void**)&p_logits,  d_logits);
    cudaGetSymbolAddress((void**)&p_rownll,  d_rownll);
    cudaGetSymbolAddress((void**)&p_nwx,     d_nwx);
    cudaGetSymbolAddress((void**)&p_nwh,     d_nwh);
    cudaGetSymbolAddress((void**)&p_nwmx,    d_nwmx);
    cudaGetSymbolAddress((void**)&p_nwmh,    d_nwmh);
    cudaGetSymbolAddress((void**)&p_xhi,     d_xhi);
    cudaGetSymbolAddress((void**)&p_xlo,     d_xlo);
    cudaGetSymbolAddress((void**)&p_wxnThi,  d_wxnThi);
    cudaGetSymbolAddress((void**)&p_wxnTlo,  d_wxnTlo);
    cudaGetSymbolAddress((void**)&p_wmxnThi, d_wmxnThi);
    cudaGetSymbolAddress((void**)&p_wmxnTlo, d_wmxnTlo);
    cudaGetSymbolAddress((void**)&p_pwhi,    d_pwhi);
    cudaGetSymbolAddress((void**)&p_pwlo,    d_pwlo);
    cudaGetSymbolAddress((void**)&p_hshi,    d_hshi);
    cudaGetSymbolAddress((void**)&p_hslo,    d_hslo);

    static bool attr_set = false;
    if (!attr_set) {
        cudaFuncSetAttribute(recur_kernel, cudaFuncAttributeMaxDynamicSharedMemorySize, RS_BYTES);
        cudaFuncSetAttribute(mma_gemm<true>,  cudaFuncAttributeMaxDynamicSharedMemorySize, GSMEM);
        cudaFuncSetAttribute(mma_gemm<false>, cudaFuncAttributeMaxDynamicSharedMemorySize, GSMEM);
        attr_set = true;
    }

    // weight norm
    zero_norms_kernel<<<16, 256>>>();
    sumsq_kernel<<<dim3(FH/256, E_/128), 256>>>(wx,  p_nwx,  E_, FH);
    sumsq_kernel<<<dim3(FH/256, H_/128), 256>>>(wh,  p_nwh,  H_, FH);
    sumsq_kernel<<<dim3(H_/256, E_/128), 256>>>(wmx, p_nwmx, E_, H_);
    sumsq_kernel<<<dim3(H_/256, H_/128), 256>>>(wmh, p_nwmh, H_, H_);
    scaleT_bf16_kernel<<<dim3(FH/32, E_/32), dim3(32,8)>>>(wx,  gx,  p_nwx,  p_wxnThi,  p_wxnTlo,  E_, FH);
    scaleT_bf16_kernel<<<dim3(H_/32, E_/32), dim3(32,8)>>>(wmx, gmx, p_nwmx, p_wmxnThi, p_wmxnTlo, E_, H_);
    scaleT_kernel<<<dim3(FH/32, H_/32), dim3(32,8)>>>(wh,  gh,  p_nwh,  p_whnT,  H_, FH);
    scaleT_kernel<<<dim3(H_/32, H_/32), dim3(32,8)>>>(wmh, gmh, p_nwmh, p_wmhnT, H_, H_);
    split_kernel<<<(int)(((size_t)V_*H_ + 255)/256), 256>>>(pred_w, p_pwhi, p_pwlo, (size_t)V_*H_);

    // embedding (bf16 split)
    embed_kernel<<<B_*T_, 128>>>(xs, embed_w, p_xhi, p_xlo);

    // input projections (tensor cores)
    mma_gemm<true ><<<dim3(FH/128, (B_*T_)/128), 256, GSMEM>>>(
        p_xhi, p_xlo, p_wxnThi, p_wxnTlo, bb, p_zx, B_*T_, FH, E_);
    mma_gemm<false><<<dim3(H_/128, (B_*T_)/128), 256, GSMEM>>>(
        p_xhi, p_xlo, p_wmxnThi, p_wmxnTlo, (const float*)nullptr, p_mx, B_*T_, H_, E_);

    // recurrence
    reset_bar_kernel<<<1, 1>>>();
    recur_kernel<<<NBLK, 256, RS_BYTES>>>(
        p_zx, p_mx, p_wmhnT, p_whnT, p_hshi, p_hslo);

    // logits (tensor cores) + loss
    mma_gemm<true><<<dim3(V_/128, (B_*T_)/128), 256, GSMEM>>>(
        p_hshi, p_hslo, p_pwhi, p_pwlo, pred_b, p_logits, B_*T_, V_, H_);
    nll_kernel<<<B_*T_, 256>>>(p_logits, ys, p_rownll);
    mean_kernel<<<1, 256>>>(p_rownll, out);
}